// round 1
// baseline (speedup 1.0000x reference)
#include <cuda_runtime.h>

// Problem constants
#define DD   512
#define TT   192
#define NNODE 64
#define BB   8
#define HH   8
#define DHH  64
#define CC   8
#define M_TOTAL (BB*TT*NNODE)   // 98304
#define BT (BB*TT)              // 1536

// ---------------- scratch (allocation-free: __device__ globals) ----------------
__device__ float g_Q[(size_t)M_TOTAL * DD];
__device__ float g_K[(size_t)M_TOTAL * DD];
__device__ float g_V[(size_t)M_TOTAL * DD];
__device__ float g_O[(size_t)M_TOTAL * DD];
__device__ int   g_cid[NNODE];

// ---------------- cluster-id decode (handles int64 OR int32 payload) ----------
__global__ void decode_cid_kernel(const int* __restrict__ raw) {
    // If the buffer is little-endian int64 (values in [0,8)), every odd 32-bit
    // word of the first 32 elements is 0. For int32 random ids the probability
    // of that is 8^-32 ~ 0.
    bool is64 = true;
    for (int i = 0; i < 32; i++) {
        if (raw[2*i + 1] != 0) { is64 = false; break; }
    }
    for (int i = 0; i < NNODE; i++) {
        g_cid[i] = is64 ? raw[2*i] : raw[i];
    }
}

// ---------------- generic GEMM: C[M,512] = A[M,512] @ W[512,512]^T + bias ------
// Tile 128x64x16, 256 threads, 8x4 micro-tile per thread.
__global__ __launch_bounds__(256) void gemm_xwT_kernel(
    const float* __restrict__ A, const float* __restrict__ W,
    const float* __restrict__ bias, float* __restrict__ C)
{
    __shared__ float As[16][132];  // k-major, padded
    __shared__ float Bs[16][68];   // k-major, padded

    const int m0 = blockIdx.x * 128;
    const int n0 = blockIdx.y * 64;
    const int tid = threadIdx.x;
    const int tx = tid & 15;   // 16 -> 64 cols (4 each)
    const int ty = tid >> 4;   // 16 -> 128 rows (8 each)

    float acc[8][4];
    #pragma unroll
    for (int i = 0; i < 8; i++)
        #pragma unroll
        for (int j = 0; j < 4; j++) acc[i][j] = 0.f;

    for (int k0 = 0; k0 < DD; k0 += 16) {
        // A tile: 128 rows x 16 k  (512 float4, 2 per thread), transposed store
        #pragma unroll
        for (int i = 0; i < 2; i++) {
            int j = tid + i * 256;
            int row = j >> 2;
            int kq = (j & 3) << 2;
            float4 v = *reinterpret_cast<const float4*>(A + (size_t)(m0 + row) * DD + k0 + kq);
            As[kq + 0][row] = v.x; As[kq + 1][row] = v.y;
            As[kq + 2][row] = v.z; As[kq + 3][row] = v.w;
        }
        // W tile: rows e = n0..n0+63, cols k0..k0+15 (B[d,e] = W[e,d])
        {
            int row = tid >> 2;        // 0..63  (e)
            int kq = (tid & 3) << 2;   // 0,4,8,12
            float4 v = *reinterpret_cast<const float4*>(W + (size_t)(n0 + row) * DD + k0 + kq);
            Bs[kq + 0][row] = v.x; Bs[kq + 1][row] = v.y;
            Bs[kq + 2][row] = v.z; Bs[kq + 3][row] = v.w;
        }
        __syncthreads();
        #pragma unroll
        for (int kk = 0; kk < 16; kk++) {
            float4 a0 = *reinterpret_cast<const float4*>(&As[kk][ty * 8]);
            float4 a1 = *reinterpret_cast<const float4*>(&As[kk][ty * 8 + 4]);
            float4 bf = *reinterpret_cast<const float4*>(&Bs[kk][tx * 4]);
            float a[8] = {a0.x, a0.y, a0.z, a0.w, a1.x, a1.y, a1.z, a1.w};
            float b[4] = {bf.x, bf.y, bf.z, bf.w};
            #pragma unroll
            for (int i = 0; i < 8; i++)
                #pragma unroll
                for (int j = 0; j < 4; j++)
                    acc[i][j] = fmaf(a[i], b[j], acc[i][j]);
        }
        __syncthreads();
    }

    float4 bv = *reinterpret_cast<const float4*>(bias + n0 + tx * 4);
    #pragma unroll
    for (int i = 0; i < 8; i++) {
        size_t row = (size_t)(m0 + ty * 8 + i);
        float4 o;
        o.x = acc[i][0] + bv.x; o.y = acc[i][1] + bv.y;
        o.z = acc[i][2] + bv.z; o.w = acc[i][3] + bv.w;
        *reinterpret_cast<float4*>(C + row * DD + n0 + tx * 4) = o;
    }
}

// ---------------- grouped K GEMM: per node n, K = X_n @ Wk[cid[n]] + bk --------
// blockIdx.z = n; rows r in [0, B*T); X row at ((r*64+n)*512). B NOT transposed.
__global__ __launch_bounds__(256) void gemm_k_kernel(
    const float* __restrict__ X, const float* __restrict__ Wk,
    const float* __restrict__ bk, float* __restrict__ Kout)
{
    __shared__ float As[16][132];
    __shared__ float Bs[16][68];

    const int r0 = blockIdx.x * 128;   // over B*T = 1536
    const int n0 = blockIdx.y * 64;
    const int n  = blockIdx.z;
    const int cid = g_cid[n];
    const float* __restrict__ Wc = Wk + (size_t)cid * DD * DD;

    const int tid = threadIdx.x;
    const int tx = tid & 15;
    const int ty = tid >> 4;

    float acc[8][4];
    #pragma unroll
    for (int i = 0; i < 8; i++)
        #pragma unroll
        for (int j = 0; j < 4; j++) acc[i][j] = 0.f;

    for (int k0 = 0; k0 < DD; k0 += 16) {
        // A tile: rows r0..r0+127 of X_n (stride 64*512 between rows)
        #pragma unroll
        for (int i = 0; i < 2; i++) {
            int j = tid + i * 256;
            int row = j >> 2;
            int kq = (j & 3) << 2;
            float4 v = *reinterpret_cast<const float4*>(
                X + ((size_t)(r0 + row) * NNODE + n) * DD + k0 + kq);
            As[kq + 0][row] = v.x; As[kq + 1][row] = v.y;
            As[kq + 2][row] = v.z; As[kq + 3][row] = v.w;
        }
        // B tile: Wc[d, e], d = k0..k0+15 (rows), e = n0..n0+63 — direct copy
        {
            int dr = tid >> 4;        // 0..15
            int ec = tid & 15;        // 0..15 -> float4
            float4 v = *reinterpret_cast<const float4*>(
                Wc + (size_t)(k0 + dr) * DD + n0 + ec * 4);
            *reinterpret_cast<float4*>(&Bs[dr][ec * 4]) = v;
        }
        __syncthreads();
        #pragma unroll
        for (int kk = 0; kk < 16; kk++) {
            float4 a0 = *reinterpret_cast<const float4*>(&As[kk][ty * 8]);
            float4 a1 = *reinterpret_cast<const float4*>(&As[kk][ty * 8 + 4]);
            float4 bf = *reinterpret_cast<const float4*>(&Bs[kk][tx * 4]);
            float a[8] = {a0.x, a0.y, a0.z, a0.w, a1.x, a1.y, a1.z, a1.w};
            float b[4] = {bf.x, bf.y, bf.z, bf.w};
            #pragma unroll
            for (int i = 0; i < 8; i++)
                #pragma unroll
                for (int j = 0; j < 4; j++)
                    acc[i][j] = fmaf(a[i], b[j], acc[i][j]);
        }
        __syncthreads();
    }

    float4 bv = *reinterpret_cast<const float4*>(bk + (size_t)cid * DD + n0 + tx * 4);
    #pragma unroll
    for (int i = 0; i < 8; i++) {
        size_t r = (size_t)(r0 + ty * 8 + i);
        float4 o;
        o.x = acc[i][0] + bv.x; o.y = acc[i][1] + bv.y;
        o.z = acc[i][2] + bv.z; o.w = acc[i][3] + bv.w;
        *reinterpret_cast<float4*>(Kout + (r * NNODE + n) * DD + n0 + tx * 4) = o;
    }
}

// ---------------- attention: one block per (b, n, h); 192 threads --------------
// K,V tiles (192x64 each) in dynamic smem (96 KB); q/o in registers; online
// softmax over chunks of 16 keys. All smem reads are warp-uniform broadcasts.
__global__ __launch_bounds__(192) void attn_kernel() {
    extern __shared__ float sm[];
    float* Ks = sm;                  // 192*64
    float* Vs = sm + TT * DHH;       // 192*64

    const int bx = blockIdx.x;           // b*512 + n*8 + h
    const int h = bx & 7;
    const int n = (bx >> 3) & 63;
    const int b = bx >> 9;
    const int tid = threadIdx.x;

    const size_t base = ((size_t)b * TT * NNODE + n) * DD + h * DHH;  // t=0
    const size_t tstride = (size_t)NNODE * DD;                        // 32768

    // cooperative, coalesced K/V load: 16 lanes cover one 256B row
    {
        const int grp  = tid >> 4;   // 0..11
        const int lane = tid & 15;   // 0..15
        #pragma unroll
        for (int it = 0; it < 16; it++) {
            int row = it * 12 + grp;
            size_t g = base + (size_t)row * tstride + lane * 4;
            *reinterpret_cast<float4*>(Ks + row * DHH + lane * 4) =
                *reinterpret_cast<const float4*>(g_K + g);
            *reinterpret_cast<float4*>(Vs + row * DHH + lane * 4) =
                *reinterpret_cast<const float4*>(g_V + g);
        }
    }

    // per-thread query row
    const int t = tid;   // 0..191
    float q[DHH];
    {
        size_t g = base + (size_t)t * tstride;
        #pragma unroll
        for (int i = 0; i < 16; i++) {
            float4 v = *reinterpret_cast<const float4*>(g_Q + g + i * 4);
            q[i*4+0] = v.x; q[i*4+1] = v.y; q[i*4+2] = v.z; q[i*4+3] = v.w;
        }
    }
    __syncthreads();

    const float scale = 0.125f;   // 1/sqrt(64)
    float m = -1e30f, l = 0.f;
    float o[DHH];
    #pragma unroll
    for (int d = 0; d < DHH; d++) o[d] = 0.f;

    for (int s0 = 0; s0 < TT; s0 += 16) {
        float sc[16];
        #pragma unroll
        for (int j = 0; j < 16; j++) {
            const float4* kr = reinterpret_cast<const float4*>(Ks + (s0 + j) * DHH);
            float acc = 0.f;
            #pragma unroll
            for (int i = 0; i < 16; i++) {
                float4 kv = kr[i];
                acc = fmaf(q[4*i+0], kv.x, acc);
                acc = fmaf(q[4*i+1], kv.y, acc);
                acc = fmaf(q[4*i+2], kv.z, acc);
                acc = fmaf(q[4*i+3], kv.w, acc);
            }
            sc[j] = acc * scale;
        }
        float cm = sc[0];
        #pragma unroll
        for (int j = 1; j < 16; j++) cm = fmaxf(cm, sc[j]);
        float mnew = fmaxf(m, cm);
        float alpha = __expf(m - mnew);
        l *= alpha;
        #pragma unroll
        for (int d = 0; d < DHH; d++) o[d] *= alpha;
        #pragma unroll
        for (int j = 0; j < 16; j++) {
            float p = __expf(sc[j] - mnew);
            l += p;
            const float4* vr = reinterpret_cast<const float4*>(Vs + (s0 + j) * DHH);
            #pragma unroll
            for (int i = 0; i < 16; i++) {
                float4 vv = vr[i];
                o[4*i+0] = fmaf(p, vv.x, o[4*i+0]);
                o[4*i+1] = fmaf(p, vv.y, o[4*i+1]);
                o[4*i+2] = fmaf(p, vv.z, o[4*i+2]);
                o[4*i+3] = fmaf(p, vv.w, o[4*i+3]);
            }
        }
        m = mnew;
    }

    const float inv = 1.f / l;
    size_t g = base + (size_t)t * tstride;
    #pragma unroll
    for (int i = 0; i < 16; i++) {
        float4 v;
        v.x = o[4*i+0] * inv; v.y = o[4*i+1] * inv;
        v.z = o[4*i+2] * inv; v.w = o[4*i+3] * inv;
        *reinterpret_cast<float4*>(g_O + g + i * 4) = v;
    }
}

// -------------------------------------------------------------------------------
extern "C" void kernel_launch(void* const* d_in, const int* in_sizes, int n_in,
                              void* d_out, int out_size) {
    const float* x      = (const float*)d_in[0];
    const float* Wq_w   = (const float*)d_in[1];
    const float* Wq_b   = (const float*)d_in[2];
    const float* Wv_w   = (const float*)d_in[3];
    const float* Wv_b   = (const float*)d_in[4];
    const float* Wk     = (const float*)d_in[5];
    const float* bk     = (const float*)d_in[6];
    const float* proj_w = (const float*)d_in[7];
    const float* proj_b = (const float*)d_in[8];
    const int*   cidraw = (const int*)d_in[9];
    float* out = (float*)d_out;

    (void)in_sizes; (void)n_in; (void)out_size;

    void *pQ, *pK, *pV, *pO;
    cudaGetSymbolAddress(&pQ, g_Q);
    cudaGetSymbolAddress(&pK, g_K);
    cudaGetSymbolAddress(&pV, g_V);
    cudaGetSymbolAddress(&pO, g_O);

    cudaFuncSetAttribute(attn_kernel,
                         cudaFuncAttributeMaxDynamicSharedMemorySize, 98304);

    decode_cid_kernel<<<1, 1>>>(cidraw);

    dim3 gq(M_TOTAL / 128, DD / 64);           // 768 x 8
    gemm_xwT_kernel<<<gq, 256>>>(x, Wq_w, Wq_b, (float*)pQ);
    gemm_xwT_kernel<<<gq, 256>>>(x, Wv_w, Wv_b, (float*)pV);

    dim3 gk(BT / 128, DD / 64, NNODE);          // 12 x 8 x 64
    gemm_k_kernel<<<gk, 256>>>(x, Wk, bk, (float*)pK);

    attn_kernel<<<BB * NNODE * HH, 192, 98304>>>();   // 4096 blocks

    gemm_xwT_kernel<<<gq, 256>>>((const float*)pO, proj_w, proj_b, out);
}

// round 4
// speedup vs baseline: 1.5786x; 1.5786x over previous
#include <cuda_runtime.h>
#include <cuda_bf16.h>
#include <cstdint>

// Problem constants
#define DD    512
#define TT    192
#define NNODE 64
#define BB    8
#define HH    8
#define DHH   64
#define CC    8
#define M_TOTAL (BB*TT*NNODE)   // 98304
#define BT (BB*TT)              // 1536

// ---------------- scratch (allocation-free: __device__ globals) ----------------
__device__ float g_Q[(size_t)M_TOTAL * DD];
__device__ float g_K[(size_t)M_TOTAL * DD];
__device__ float g_V[(size_t)M_TOTAL * DD];
__device__ int   g_cid[NNODE];
// x and attention-output in bf16 hi/lo split form
__device__ __nv_bfloat16 g_Xhi[(size_t)M_TOTAL * DD];
__device__ __nv_bfloat16 g_Xlo[(size_t)M_TOTAL * DD];
__device__ __nv_bfloat16 g_Ohi[(size_t)M_TOTAL * DD];
__device__ __nv_bfloat16 g_Olo[(size_t)M_TOTAL * DD];
// converted weights: [0]=Wq, [1]=Wv, [2]=proj (K-major as given, W[e][d]),
// [3+c] = Wk[c] transposed to K-major (out[e][d] = Wk[c][d][e])
#define NW 11
__device__ __nv_bfloat16 g_Whi[(size_t)NW * DD * DD];
__device__ __nv_bfloat16 g_Wlo[(size_t)NW * DD * DD];

// ================= PTX helpers (NO arch-'a' instructions: sm_80-safe) ==========
__device__ __forceinline__ uint32_t smem_u32(const void* p) {
    uint32_t a;
    asm("{ .reg .u64 t; cvta.to.shared.u64 t, %1; cvt.u32.u64 %0, t; }" : "=r"(a) : "l"(p));
    return a;
}
#define CP16(saddr, gptr) \
    asm volatile("cp.async.cg.shared.global [%0], [%1], 16;" \
        :: "r"((uint32_t)(saddr)), "l"(gptr))
#define CP_COMMIT() asm volatile("cp.async.commit_group;")
#define CP_WAIT(n)  asm volatile("cp.async.wait_group %0;" :: "n"(n))
#define LDSM4(r, addr) \
    asm volatile("ldmatrix.sync.aligned.m8n8.x4.shared.b16 {%0,%1,%2,%3}, [%4];" \
        : "=r"((r)[0]), "=r"((r)[1]), "=r"((r)[2]), "=r"((r)[3]) : "r"((uint32_t)(addr)))
#define MMA16816(d, a, b) \
    asm volatile("mma.sync.aligned.m16n8k16.row.col.f32.bf16.bf16.f32 " \
        "{%0,%1,%2,%3}, {%4,%5,%6,%7}, {%8,%9}, {%0,%1,%2,%3};" \
        : "+f"((d)[0]), "+f"((d)[1]), "+f"((d)[2]), "+f"((d)[3]) \
        : "r"((a)[0]), "r"((a)[1]), "r"((a)[2]), "r"((a)[3]), \
          "r"((b)[0]), "r"((b)[1]))

__device__ __forceinline__ void hilo(float v, uint32_t& h, uint32_t& l) {
    __nv_bfloat16 hb = __float2bfloat16(v);
    h = (uint32_t)__bfloat16_as_ushort(hb);
    l = (uint32_t)__bfloat16_as_ushort(__float2bfloat16(v - __bfloat162float(hb)));
}

// ---------------- cluster-id decode (handles int64 OR int32 payload) ----------
__global__ void decode_cid_kernel(const int* __restrict__ raw) {
    bool is64 = true;
    for (int i = 0; i < 32; i++) if (raw[2*i + 1] != 0) { is64 = false; break; }
    for (int i = 0; i < NNODE; i++) g_cid[i] = is64 ? raw[2*i] : raw[i];
}

// ---------------- weight conversion prepass: fp32 -> bf16 hi/lo ---------------
__global__ __launch_bounds__(256) void convert_weights_kernel(
    const float* __restrict__ Wq, const float* __restrict__ Wv,
    const float* __restrict__ proj, const float* __restrict__ Wk)
{
    int idx = blockIdx.x * 256 + threadIdx.x;
    int w = idx >> 18;
    int rc = idx & 262143;
    float v;
    if (w < 3) {
        const float* src = (w == 0) ? Wq : ((w == 1) ? Wv : proj);
        v = src[rc];
    } else {
        int e = rc >> 9, d = rc & 511;
        v = Wk[(((size_t)(w - 3)) * DD + d) * DD + e];   // transpose to K-major
    }
    uint32_t h, l;
    hilo(v, h, l);
    g_Whi[idx] = __ushort_as_bfloat16((unsigned short)h);
    g_Wlo[idx] = __ushort_as_bfloat16((unsigned short)l);
}

// ---------------- x conversion prepass --------------------------------------
__global__ __launch_bounds__(256) void convert_x_kernel(const float* __restrict__ x) {
    size_t i = ((size_t)blockIdx.x * 256 + threadIdx.x) * 4;
    float4 v = *reinterpret_cast<const float4*>(x + i);
    uint32_t h[4], l[4];
    hilo(v.x, h[0], l[0]); hilo(v.y, h[1], l[1]);
    hilo(v.z, h[2], l[2]); hilo(v.w, h[3], l[3]);
    uint2 hp, lp;
    hp.x = h[0] | (h[1] << 16); hp.y = h[2] | (h[3] << 16);
    lp.x = l[0] | (l[1] << 16); lp.y = l[2] | (l[3] << 16);
    *reinterpret_cast<uint2*>(g_Xhi + i) = hp;
    *reinterpret_cast<uint2*>(g_Xlo + i) = lp;
}

// ================= mma.sync GEMM: C = A @ W^T + bias ===========================
// 3-term bf16 split: Ahi*Bhi + Ahi*Blo + Alo*Bhi, fp32 accumulation.
// Block 128x128, 8 warps (2x4), warp tile 64x32, K-chunk 32, double-buffered.
// smem row stride 80B (32 bf16 data + pad) -> conflict-free ldmatrix.
#define ROWB 80
#define STG_BYTES (4 * 128 * ROWB)          // 40960 per stage (Ahi,Alo,Bhi,Blo)
#define SMEM_GEMM (2 * STG_BYTES)           // 81920

template<int GROUPED>
__global__ __launch_bounds__(256, 1) void gemm_mma_kernel(
    const __nv_bfloat16* __restrict__ Ahi, const __nv_bfloat16* __restrict__ Alo,
    const float* __restrict__ bias_plain, const float* __restrict__ bk,
    float* __restrict__ Cglob, int widx)
{
    extern __shared__ char smem[];
    const uint32_t sbase = smem_u32(smem);
    const int tid = threadIdx.x;
    const int lane = tid & 31, wid = tid >> 5;
    const int warp_m = wid & 1;       // 2 -> 64 rows each
    const int warp_n = wid >> 1;      // 4 -> 32 cols each
    const int n0 = blockIdx.x * 128;
    const int m0 = blockIdx.y * 128;

    int nz = 0, cid = 0;
    const __nv_bfloat16 *Bhi, *Blo;
    if (GROUPED) {
        nz = blockIdx.z;
        cid = g_cid[nz];
        Bhi = g_Whi + (size_t)(3 + cid) * DD * DD;
        Blo = g_Wlo + (size_t)(3 + cid) * DD * DD;
    } else {
        Bhi = g_Whi + (size_t)widx * DD * DD;
        Blo = g_Wlo + (size_t)widx * DD * DD;
    }

    // per-thread load coordinates: 2 x (row, 16B col) covering 128x(4x16B)
    const int lrow0 = tid >> 1;                 // tid*2/4
    // u = tid*2 + i -> row = u>>2, c = u&3
    float acc[4][4][4];
    #pragma unroll
    for (int a = 0; a < 4; a++)
        #pragma unroll
        for (int b = 0; b < 4; b++)
            #pragma unroll
            for (int c = 0; c < 4; c++) acc[a][b][c] = 0.f;
    (void)lrow0;

    auto load_chunk = [&](int kc, int s) {
        const int k0 = kc * 32;
        const uint32_t st = sbase + s * STG_BYTES;
        #pragma unroll
        for (int i = 0; i < 2; i++) {
            const int u = tid * 2 + i;
            const int row = u >> 2, c = u & 3;
            const uint32_t so = (uint32_t)(row * ROWB + c * 16);
            size_t arow = GROUPED ? ((size_t)(m0 + row) * NNODE + nz)
                                  : (size_t)(m0 + row);
            const __nv_bfloat16* ga  = Ahi + arow * DD + k0 + c * 8;
            const __nv_bfloat16* gal = Alo + arow * DD + k0 + c * 8;
            CP16(st + so, ga);
            CP16(st + 10240 + so, gal);
            const size_t brow = (size_t)(n0 + row) * DD + k0 + c * 8;
            CP16(st + 20480 + so, Bhi + brow);
            CP16(st + 30720 + so, Blo + brow);
        }
    };

    load_chunk(0, 0);
    CP_COMMIT();

    for (int kc = 0; kc < 16; kc++) {
        const int s = kc & 1;
        if (kc < 15) {
            load_chunk(kc + 1, s ^ 1);
            CP_COMMIT();
            CP_WAIT(1);
        } else {
            CP_WAIT(0);
        }
        __syncthreads();

        const uint32_t sa  = sbase + s * STG_BYTES;
        const uint32_t sal = sa + 10240;
        const uint32_t sb  = sa + 20480;
        const uint32_t sbl = sa + 30720;

        #pragma unroll
        for (int ks = 0; ks < 2; ks++) {
            uint32_t ahi[4][4], alo[4][4], bhi[4][2], blo[4][2];
            #pragma unroll
            for (int mi = 0; mi < 4; mi++) {
                const uint32_t ao = (uint32_t)((warp_m * 64 + mi * 16 + (lane & 15)) * ROWB
                                               + ks * 32 + (lane >> 4) * 16);
                LDSM4(ahi[mi], sa + ao);
                LDSM4(alo[mi], sal + ao);
            }
            #pragma unroll
            for (int nb = 0; nb < 2; nb++) {
                const uint32_t bo = (uint32_t)((warp_n * 32 + nb * 16 + ((lane >> 4) << 3)
                                                + (lane & 7)) * ROWB
                                               + ks * 32 + ((lane >> 3) & 1) * 16);
                uint32_t r[4];
                LDSM4(r, sb + bo);
                bhi[nb*2][0] = r[0]; bhi[nb*2][1] = r[1];
                bhi[nb*2+1][0] = r[2]; bhi[nb*2+1][1] = r[3];
                LDSM4(r, sbl + bo);
                blo[nb*2][0] = r[0]; blo[nb*2][1] = r[1];
                blo[nb*2+1][0] = r[2]; blo[nb*2+1][1] = r[3];
            }
            #pragma unroll
            for (int mi = 0; mi < 4; mi++)
                #pragma unroll
                for (int nj = 0; nj < 4; nj++) {
                    MMA16816(acc[mi][nj], ahi[mi], bhi[nj]);
                    MMA16816(acc[mi][nj], ahi[mi], blo[nj]);
                    MMA16816(acc[mi][nj], alo[mi], bhi[nj]);
                }
        }
        __syncthreads();
    }

    // epilogue: bias add + fp32 store
    const float* bias = GROUPED ? (bk + (size_t)cid * DD) : bias_plain;
    #pragma unroll
    for (int mi = 0; mi < 4; mi++) {
        #pragma unroll
        for (int nj = 0; nj < 4; nj++) {
            const int col = n0 + warp_n * 32 + nj * 8 + (lane & 3) * 2;
            const float b0 = bias[col], b1 = bias[col + 1];
            const int r0 = m0 + warp_m * 64 + mi * 16 + (lane >> 2);
            const size_t ro0 = GROUPED ? ((size_t)r0 * NNODE + nz) : (size_t)r0;
            const size_t ro1 = GROUPED ? ((size_t)(r0 + 8) * NNODE + nz) : (size_t)(r0 + 8);
            float2 v0, v1;
            v0.x = acc[mi][nj][0] + b0; v0.y = acc[mi][nj][1] + b1;
            v1.x = acc[mi][nj][2] + b0; v1.y = acc[mi][nj][3] + b1;
            *reinterpret_cast<float2*>(Cglob + ro0 * DD + col) = v0;
            *reinterpret_cast<float2*>(Cglob + ro1 * DD + col) = v1;
        }
    }
}

// ---------------- attention: one block per (b, n, h); 192 threads --------------
// Emits O as bf16 hi/lo for the proj GEMM.
__global__ __launch_bounds__(192) void attn_kernel() {
    extern __shared__ float sm[];
    float* Ks = sm;
    float* Vs = sm + TT * DHH;

    const int bx = blockIdx.x;
    const int h = bx & 7;
    const int n = (bx >> 3) & 63;
    const int b = bx >> 9;
    const int tid = threadIdx.x;

    const size_t base = ((size_t)b * TT * NNODE + n) * DD + h * DHH;
    const size_t tstride = (size_t)NNODE * DD;

    {
        const int grp  = tid >> 4;
        const int lane = tid & 15;
        #pragma unroll
        for (int it = 0; it < 16; it++) {
            int row = it * 12 + grp;
            size_t g = base + (size_t)row * tstride + lane * 4;
            *reinterpret_cast<float4*>(Ks + row * DHH + lane * 4) =
                *reinterpret_cast<const float4*>(g_K + g);
            *reinterpret_cast<float4*>(Vs + row * DHH + lane * 4) =
                *reinterpret_cast<const float4*>(g_V + g);
        }
    }

    const int t = tid;
    float q[DHH];
    {
        size_t g = base + (size_t)t * tstride;
        #pragma unroll
        for (int i = 0; i < 16; i++) {
            float4 v = *reinterpret_cast<const float4*>(g_Q + g + i * 4);
            q[i*4+0] = v.x; q[i*4+1] = v.y; q[i*4+2] = v.z; q[i*4+3] = v.w;
        }
    }
    __syncthreads();

    const float scale = 0.125f;
    float m = -1e30f, l = 0.f;
    float o[DHH];
    #pragma unroll
    for (int d = 0; d < DHH; d++) o[d] = 0.f;

    for (int s0 = 0; s0 < TT; s0 += 16) {
        float sc[16];
        #pragma unroll
        for (int j = 0; j < 16; j++) {
            const float4* kr = reinterpret_cast<const float4*>(Ks + (s0 + j) * DHH);
            float acc = 0.f;
            #pragma unroll
            for (int i = 0; i < 16; i++) {
                float4 kv = kr[i];
                acc = fmaf(q[4*i+0], kv.x, acc);
                acc = fmaf(q[4*i+1], kv.y, acc);
                acc = fmaf(q[4*i+2], kv.z, acc);
                acc = fmaf(q[4*i+3], kv.w, acc);
            }
            sc[j] = acc * scale;
        }
        float cm = sc[0];
        #pragma unroll
        for (int j = 1; j < 16; j++) cm = fmaxf(cm, sc[j]);
        float mnew = fmaxf(m, cm);
        float alpha = __expf(m - mnew);
        l *= alpha;
        #pragma unroll
        for (int d = 0; d < DHH; d++) o[d] *= alpha;
        #pragma unroll
        for (int j = 0; j < 16; j++) {
            float p = __expf(sc[j] - mnew);
            l += p;
            const float4* vr = reinterpret_cast<const float4*>(Vs + (s0 + j) * DHH);
            #pragma unroll
            for (int i = 0; i < 16; i++) {
                float4 vv = vr[i];
                o[4*i+0] = fmaf(p, vv.x, o[4*i+0]);
                o[4*i+1] = fmaf(p, vv.y, o[4*i+1]);
                o[4*i+2] = fmaf(p, vv.z, o[4*i+2]);
                o[4*i+3] = fmaf(p, vv.w, o[4*i+3]);
            }
        }
        m = mnew;
    }

    const float inv = 1.f / l;
    size_t g = base + (size_t)t * tstride;
    #pragma unroll
    for (int i = 0; i < 16; i++) {
        uint32_t h4[4], l4[4];
        hilo(o[4*i+0] * inv, h4[0], l4[0]);
        hilo(o[4*i+1] * inv, h4[1], l4[1]);
        hilo(o[4*i+2] * inv, h4[2], l4[2]);
        hilo(o[4*i+3] * inv, h4[3], l4[3]);
        uint2 hp, lp;
        hp.x = h4[0] | (h4[1] << 16); hp.y = h4[2] | (h4[3] << 16);
        lp.x = l4[0] | (l4[1] << 16); lp.y = l4[2] | (l4[3] << 16);
        *reinterpret_cast<uint2*>(g_Ohi + g + i * 4) = hp;
        *reinterpret_cast<uint2*>(g_Olo + g + i * 4) = lp;
    }
}

// -------------------------------------------------------------------------------
extern "C" void kernel_launch(void* const* d_in, const int* in_sizes, int n_in,
                              void* d_out, int out_size) {
    const float* x      = (const float*)d_in[0];
    const float* Wq_w   = (const float*)d_in[1];
    const float* Wq_b   = (const float*)d_in[2];
    const float* Wv_w   = (const float*)d_in[3];
    const float* Wv_b   = (const float*)d_in[4];
    const float* Wk     = (const float*)d_in[5];
    const float* bk     = (const float*)d_in[6];
    const float* proj_w = (const float*)d_in[7];
    const float* proj_b = (const float*)d_in[8];
    const int*   cidraw = (const int*)d_in[9];
    float* out = (float*)d_out;

    (void)in_sizes; (void)n_in; (void)out_size;

    void *pQ, *pK, *pV, *pXhi, *pXlo, *pOhi, *pOlo;
    cudaGetSymbolAddress(&pQ, g_Q);
    cudaGetSymbolAddress(&pK, g_K);
    cudaGetSymbolAddress(&pV, g_V);
    cudaGetSymbolAddress(&pXhi, g_Xhi);
    cudaGetSymbolAddress(&pXlo, g_Xlo);
    cudaGetSymbolAddress(&pOhi, g_Ohi);
    cudaGetSymbolAddress(&pOlo, g_Olo);

    cudaFuncSetAttribute(attn_kernel,
                         cudaFuncAttributeMaxDynamicSharedMemorySize, 98304);
    cudaFuncSetAttribute(gemm_mma_kernel<0>,
                         cudaFuncAttributeMaxDynamicSharedMemorySize, SMEM_GEMM);
    cudaFuncSetAttribute(gemm_mma_kernel<1>,
                         cudaFuncAttributeMaxDynamicSharedMemorySize, SMEM_GEMM);

    decode_cid_kernel<<<1, 1>>>(cidraw);
    convert_weights_kernel<<<(NW * DD * DD) / 256, 256>>>(Wq_w, Wv_w, proj_w, Wk);
    convert_x_kernel<<<(M_TOTAL * (size_t)DD) / 1024, 256>>>(x);

    dim3 gp(4, M_TOTAL / 128);                 // n-fastest for L2 reuse of A
    gemm_mma_kernel<0><<<gp, 256, SMEM_GEMM>>>(
        (const __nv_bfloat16*)pXhi, (const __nv_bfloat16*)pXlo,
        Wq_b, nullptr, (float*)pQ, 0);
    gemm_mma_kernel<0><<<gp, 256, SMEM_GEMM>>>(
        (const __nv_bfloat16*)pXhi, (const __nv_bfloat16*)pXlo,
        Wv_b, nullptr, (float*)pV, 1);

    dim3 gk(4, BT / 128, NNODE);
    gemm_mma_kernel<1><<<gk, 256, SMEM_GEMM>>>(
        (const __nv_bfloat16*)pXhi, (const __nv_bfloat16*)pXlo,
        nullptr, bk, (float*)pK, -1);

    attn_kernel<<<BB * NNODE * HH, 192, 98304>>>();   // 4096 blocks

    gemm_mma_kernel<0><<<gp, 256, SMEM_GEMM>>>(
        (const __nv_bfloat16*)pOhi, (const __nv_bfloat16*)pOlo,
        proj_b, nullptr, out, 2);
}

// round 5
// speedup vs baseline: 2.4472x; 1.5503x over previous
#include <cuda_runtime.h>
#include <cuda_bf16.h>
#include <cstdint>

// Problem constants
#define DD    512
#define TT    192
#define NNODE 64
#define BB    8
#define HH    8
#define DHH   64
#define CC    8
#define M_TOTAL (BB*TT*NNODE)   // 98304
#define BT (BB*TT)              // 1536

// ---------------- scratch (allocation-free: __device__ globals) ----------------
__device__ int   g_cid[NNODE];
// all activations in bf16 hi/lo split form
__device__ __nv_bfloat16 g_Xhi[(size_t)M_TOTAL * DD];
__device__ __nv_bfloat16 g_Xlo[(size_t)M_TOTAL * DD];
__device__ __nv_bfloat16 g_Qhi[(size_t)M_TOTAL * DD];
__device__ __nv_bfloat16 g_Qlo[(size_t)M_TOTAL * DD];
__device__ __nv_bfloat16 g_Khi[(size_t)M_TOTAL * DD];
__device__ __nv_bfloat16 g_Klo[(size_t)M_TOTAL * DD];
__device__ __nv_bfloat16 g_Vhi[(size_t)M_TOTAL * DD];
__device__ __nv_bfloat16 g_Vlo[(size_t)M_TOTAL * DD];
__device__ __nv_bfloat16 g_Ohi[(size_t)M_TOTAL * DD];
__device__ __nv_bfloat16 g_Olo[(size_t)M_TOTAL * DD];
// converted weights: [0]=Wq, [1]=Wv, [2]=proj (K-major as given, W[e][d]),
// [3+c] = Wk[c] transposed to K-major
#define NW 11
__device__ __nv_bfloat16 g_Whi[(size_t)NW * DD * DD];
__device__ __nv_bfloat16 g_Wlo[(size_t)NW * DD * DD];

// ================= PTX helpers (NO arch-'a' instructions: sm_80-safe) ==========
__device__ __forceinline__ uint32_t smem_u32(const void* p) {
    uint32_t a;
    asm("{ .reg .u64 t; cvta.to.shared.u64 t, %1; cvt.u32.u64 %0, t; }" : "=r"(a) : "l"(p));
    return a;
}
#define CP16(saddr, gptr) \
    asm volatile("cp.async.cg.shared.global [%0], [%1], 16;" \
        :: "r"((uint32_t)(saddr)), "l"(gptr))
#define CP_COMMIT() asm volatile("cp.async.commit_group;")
#define CP_WAIT(n)  asm volatile("cp.async.wait_group %0;" :: "n"(n))
#define LDSM4(r, addr) \
    asm volatile("ldmatrix.sync.aligned.m8n8.x4.shared.b16 {%0,%1,%2,%3}, [%4];" \
        : "=r"((r)[0]), "=r"((r)[1]), "=r"((r)[2]), "=r"((r)[3]) : "r"((uint32_t)(addr)))
#define LDSM4T(r, addr) \
    asm volatile("ldmatrix.sync.aligned.m8n8.x4.trans.shared.b16 {%0,%1,%2,%3}, [%4];" \
        : "=r"((r)[0]), "=r"((r)[1]), "=r"((r)[2]), "=r"((r)[3]) : "r"((uint32_t)(addr)))
#define MMA16816(d, a, b) \
    asm volatile("mma.sync.aligned.m16n8k16.row.col.f32.bf16.bf16.f32 " \
        "{%0,%1,%2,%3}, {%4,%5,%6,%7}, {%8,%9}, {%0,%1,%2,%3};" \
        : "+f"((d)[0]), "+f"((d)[1]), "+f"((d)[2]), "+f"((d)[3]) \
        : "r"((a)[0]), "r"((a)[1]), "r"((a)[2]), "r"((a)[3]), \
          "r"((b)[0]), "r"((b)[1]))

__device__ __forceinline__ void hilo(float v, uint32_t& h, uint32_t& l) {
    __nv_bfloat16 hb = __float2bfloat16(v);
    h = (uint32_t)__bfloat16_as_ushort(hb);
    l = (uint32_t)__bfloat16_as_ushort(__float2bfloat16(v - __bfloat162float(hb)));
}
// pack two floats -> one u32 of bf16-hi pair + one u32 of bf16-lo pair
__device__ __forceinline__ void hilo2(float v0, float v1, uint32_t& hp, uint32_t& lp) {
    uint32_t h0, l0, h1, l1;
    hilo(v0, h0, l0); hilo(v1, h1, l1);
    hp = h0 | (h1 << 16);
    lp = l0 | (l1 << 16);
}

// ---------------- cluster-id decode (handles int64 OR int32 payload) ----------
__global__ void decode_cid_kernel(const int* __restrict__ raw) {
    bool is64 = true;
    for (int i = 0; i < 32; i++) if (raw[2*i + 1] != 0) { is64 = false; break; }
    for (int i = 0; i < NNODE; i++) g_cid[i] = is64 ? raw[2*i] : raw[i];
}

// ---------------- weight conversion prepass: fp32 -> bf16 hi/lo ---------------
__global__ __launch_bounds__(256) void convert_weights_kernel(
    const float* __restrict__ Wq, const float* __restrict__ Wv,
    const float* __restrict__ proj, const float* __restrict__ Wk)
{
    int idx = blockIdx.x * 256 + threadIdx.x;
    int w = idx >> 18;
    int rc = idx & 262143;
    float v;
    if (w < 3) {
        const float* src = (w == 0) ? Wq : ((w == 1) ? Wv : proj);
        v = src[rc];
    } else {
        int e = rc >> 9, d = rc & 511;
        v = Wk[(((size_t)(w - 3)) * DD + d) * DD + e];   // transpose to K-major
    }
    uint32_t h, l;
    hilo(v, h, l);
    g_Whi[idx] = __ushort_as_bfloat16((unsigned short)h);
    g_Wlo[idx] = __ushort_as_bfloat16((unsigned short)l);
}

// ---------------- x conversion prepass ----------------------------------------
__global__ __launch_bounds__(256) void convert_x_kernel(const float* __restrict__ x) {
    size_t i = ((size_t)blockIdx.x * 256 + threadIdx.x) * 4;
    float4 v = *reinterpret_cast<const float4*>(x + i);
    uint32_t hp0, lp0, hp1, lp1;
    hilo2(v.x, v.y, hp0, lp0);
    hilo2(v.z, v.w, hp1, lp1);
    uint2 hp, lp;
    hp.x = hp0; hp.y = hp1; lp.x = lp0; lp.y = lp1;
    *reinterpret_cast<uint2*>(g_Xhi + i) = hp;
    *reinterpret_cast<uint2*>(g_Xlo + i) = lp;
}

// ================= mma.sync GEMM: C = A @ W^T + bias ===========================
// 3-term bf16 split. Block 128x128, 8 warps (2x4), warp 64x32, K-chunk 32,
// double-buffered cp.async. Row stride 80B -> conflict-free ldmatrix.
// HILO=1: write bf16 hi/lo outputs; HILO=0: fp32 output.
#define ROWB 80
#define STG_BYTES (4 * 128 * ROWB)          // 40960 per stage
#define SMEM_GEMM (2 * STG_BYTES)           // 81920

template<int GROUPED, int HILO>
__global__ __launch_bounds__(256, 2) void gemm_mma_kernel(
    const __nv_bfloat16* __restrict__ Ahi, const __nv_bfloat16* __restrict__ Alo,
    const float* __restrict__ bias_plain, const float* __restrict__ bk,
    float* __restrict__ Cf32,
    __nv_bfloat16* __restrict__ Chi, __nv_bfloat16* __restrict__ Clo,
    int widx)
{
    extern __shared__ char smem[];
    const uint32_t sbase = smem_u32(smem);
    const int tid = threadIdx.x;
    const int lane = tid & 31, wid = tid >> 5;
    const int warp_m = wid & 1;
    const int warp_n = wid >> 1;
    const int n0 = blockIdx.x * 128;
    const int m0 = blockIdx.y * 128;

    int nz = 0, cid = 0;
    const __nv_bfloat16 *Bhi, *Blo;
    if (GROUPED) {
        nz = blockIdx.z;
        cid = g_cid[nz];
        Bhi = g_Whi + (size_t)(3 + cid) * DD * DD;
        Blo = g_Wlo + (size_t)(3 + cid) * DD * DD;
    } else {
        Bhi = g_Whi + (size_t)widx * DD * DD;
        Blo = g_Wlo + (size_t)widx * DD * DD;
    }

    float acc[4][4][4];
    #pragma unroll
    for (int a = 0; a < 4; a++)
        #pragma unroll
        for (int b = 0; b < 4; b++)
            #pragma unroll
            for (int c = 0; c < 4; c++) acc[a][b][c] = 0.f;

    auto load_chunk = [&](int kc, int s) {
        const int k0 = kc * 32;
        const uint32_t st = sbase + s * STG_BYTES;
        #pragma unroll
        for (int i = 0; i < 2; i++) {
            const int u = tid * 2 + i;
            const int row = u >> 2, c = u & 3;
            const uint32_t so = (uint32_t)(row * ROWB + c * 16);
            size_t arow = GROUPED ? ((size_t)(m0 + row) * NNODE + nz)
                                  : (size_t)(m0 + row);
            CP16(st + so, Ahi + arow * DD + k0 + c * 8);
            CP16(st + 10240 + so, Alo + arow * DD + k0 + c * 8);
            const size_t brow = (size_t)(n0 + row) * DD + k0 + c * 8;
            CP16(st + 20480 + so, Bhi + brow);
            CP16(st + 30720 + so, Blo + brow);
        }
    };

    load_chunk(0, 0);
    CP_COMMIT();

    for (int kc = 0; kc < 16; kc++) {
        const int s = kc & 1;
        if (kc < 15) {
            load_chunk(kc + 1, s ^ 1);
            CP_COMMIT();
            CP_WAIT(1);
        } else {
            CP_WAIT(0);
        }
        __syncthreads();

        const uint32_t sa  = sbase + s * STG_BYTES;
        const uint32_t sal = sa + 10240;
        const uint32_t sb  = sa + 20480;
        const uint32_t sbl = sa + 30720;

        #pragma unroll
        for (int ks = 0; ks < 2; ks++) {
            uint32_t ahi[4][4], alo[4][4], bhi[4][2], blo[4][2];
            #pragma unroll
            for (int mi = 0; mi < 4; mi++) {
                const uint32_t ao = (uint32_t)((warp_m * 64 + mi * 16 + (lane & 15)) * ROWB
                                               + ks * 32 + (lane >> 4) * 16);
                LDSM4(ahi[mi], sa + ao);
                LDSM4(alo[mi], sal + ao);
            }
            #pragma unroll
            for (int nb = 0; nb < 2; nb++) {
                const uint32_t bo = (uint32_t)((warp_n * 32 + nb * 16 + ((lane >> 4) << 3)
                                                + (lane & 7)) * ROWB
                                               + ks * 32 + ((lane >> 3) & 1) * 16);
                uint32_t r[4];
                LDSM4(r, sb + bo);
                bhi[nb*2][0] = r[0]; bhi[nb*2][1] = r[1];
                bhi[nb*2+1][0] = r[2]; bhi[nb*2+1][1] = r[3];
                LDSM4(r, sbl + bo);
                blo[nb*2][0] = r[0]; blo[nb*2][1] = r[1];
                blo[nb*2+1][0] = r[2]; blo[nb*2+1][1] = r[3];
            }
            #pragma unroll
            for (int mi = 0; mi < 4; mi++)
                #pragma unroll
                for (int nj = 0; nj < 4; nj++) {
                    MMA16816(acc[mi][nj], ahi[mi], bhi[nj]);
                    MMA16816(acc[mi][nj], ahi[mi], blo[nj]);
                    MMA16816(acc[mi][nj], alo[mi], bhi[nj]);
                }
        }
        __syncthreads();
    }

    // epilogue
    const float* bias = GROUPED ? (bk + (size_t)cid * DD) : bias_plain;
    #pragma unroll
    for (int mi = 0; mi < 4; mi++) {
        #pragma unroll
        for (int nj = 0; nj < 4; nj++) {
            const int col = n0 + warp_n * 32 + nj * 8 + (lane & 3) * 2;
            const float b0 = bias[col], b1 = bias[col + 1];
            const int r0 = m0 + warp_m * 64 + mi * 16 + (lane >> 2);
            const size_t ro0 = GROUPED ? ((size_t)r0 * NNODE + nz) : (size_t)r0;
            const size_t ro1 = GROUPED ? ((size_t)(r0 + 8) * NNODE + nz) : (size_t)(r0 + 8);
            float v0 = acc[mi][nj][0] + b0, v1 = acc[mi][nj][1] + b1;
            float v2 = acc[mi][nj][2] + b0, v3 = acc[mi][nj][3] + b1;
            if (HILO) {
                uint32_t hp, lp;
                hilo2(v0, v1, hp, lp);
                *reinterpret_cast<uint32_t*>(Chi + ro0 * DD + col) = hp;
                *reinterpret_cast<uint32_t*>(Clo + ro0 * DD + col) = lp;
                hilo2(v2, v3, hp, lp);
                *reinterpret_cast<uint32_t*>(Chi + ro1 * DD + col) = hp;
                *reinterpret_cast<uint32_t*>(Clo + ro1 * DD + col) = lp;
            } else {
                float2 w0; w0.x = v0; w0.y = v1;
                float2 w1; w1.x = v2; w1.y = v3;
                *reinterpret_cast<float2*>(Cf32 + ro0 * DD + col) = w0;
                *reinterpret_cast<float2*>(Cf32 + ro1 * DD + col) = w1;
            }
        }
    }
}

// ================= tensor-core attention ======================================
// Block = (b,n,h), 384 threads (12 warps); warp w owns query rows [16w,16w+16).
// Q/K/V bf16 hi/lo in smem, row stride 144B. S=QK^T and O=PV via 3-term splits.
#define AROW 144
#define ATEN (192 * AROW)            // 27648 per sub-tensor
#define ASMEM (6 * ATEN)             // 165888

__global__ __launch_bounds__(384, 1) void attn_mma_kernel() {
    extern __shared__ char smem[];
    const uint32_t sbase = smem_u32(smem);
    const int tid = threadIdx.x;
    const int lane = tid & 31, w = tid >> 5;

    const int bx = blockIdx.x;
    const int h = bx & 7;
    const int n = (bx >> 3) & 63;
    const int b = bx >> 9;
    const size_t base = ((size_t)b * TT * NNODE + n) * DD + h * DHH;
    const size_t tstride = (size_t)NNODE * DD;   // 32768

    // ---- stage Q/K/V hi/lo into smem (each: 192 rows x 128B, stride 144B) ----
    {
        const __nv_bfloat16* t0 = g_Qhi + base;
        const __nv_bfloat16* t1 = g_Qlo + base;
        const __nv_bfloat16* t2 = g_Khi + base;
        const __nv_bfloat16* t3 = g_Klo + base;
        const __nv_bfloat16* t4 = g_Vhi + base;
        const __nv_bfloat16* t5 = g_Vlo + base;
        #pragma unroll
        for (int ti = 0; ti < 6; ti++) {
            const __nv_bfloat16* tp = (ti == 0) ? t0 : (ti == 1) ? t1 : (ti == 2) ? t2
                                    : (ti == 3) ? t3 : (ti == 4) ? t4 : t5;
            char* sp = smem + ti * ATEN;
            #pragma unroll
            for (int i = 0; i < 4; i++) {
                const int c = tid + i * 384;        // 0..1535
                const int r = c >> 3, o = c & 7;
                *reinterpret_cast<uint4*>(sp + r * AROW + o * 16) =
                    *reinterpret_cast<const uint4*>(tp + (size_t)r * tstride + o * 8);
            }
        }
    }
    __syncthreads();

    const uint32_t sQH = sbase, sQL = sbase + ATEN;
    const uint32_t sKH = sbase + 2 * ATEN, sKL = sbase + 3 * ATEN;
    const uint32_t sVH = sbase + 4 * ATEN, sVL = sbase + 5 * ATEN;

    // ---- preload Q fragments (16 rows x 64 k, hi+lo) ----
    uint32_t qh[4][4], ql[4][4];
    {
        const int qrow = w * 16 + (lane & 15);
        #pragma unroll
        for (int kt = 0; kt < 4; kt++) {
            const uint32_t ao = (uint32_t)(qrow * AROW + kt * 32 + (lane >> 4) * 16);
            LDSM4(qh[kt], sQH + ao);
            LDSM4(ql[kt], sQL + ao);
        }
    }

    float oacc[8][4];
    #pragma unroll
    for (int i = 0; i < 8; i++)
        #pragma unroll
        for (int j = 0; j < 4; j++) oacc[i][j] = 0.f;
    float m0 = -1e30f, m1 = -1e30f, l0 = 0.f, l1 = 0.f;

    for (int s0 = 0; s0 < TT; s0 += 16) {
        // ---- S = Q K^T (3-term) ----
        float sa0[4] = {0.f, 0.f, 0.f, 0.f};
        float sa1[4] = {0.f, 0.f, 0.f, 0.f};
        #pragma unroll
        for (int kt = 0; kt < 4; kt++) {
            const uint32_t bo = (uint32_t)((s0 + ((lane >> 4) << 3) + (lane & 7)) * AROW
                                           + kt * 32 + ((lane >> 3) & 1) * 16);
            uint32_t rh[4], rl[4];
            LDSM4(rh, sKH + bo);
            LDSM4(rl, sKL + bo);
            uint32_t bh0[2] = {rh[0], rh[1]}, bh1[2] = {rh[2], rh[3]};
            uint32_t bl0[2] = {rl[0], rl[1]}, bl1[2] = {rl[2], rl[3]};
            MMA16816(sa0, qh[kt], bh0);
            MMA16816(sa0, qh[kt], bl0);
            MMA16816(sa0, ql[kt], bh0);
            MMA16816(sa1, qh[kt], bh1);
            MMA16816(sa1, qh[kt], bl1);
            MMA16816(sa1, ql[kt], bh1);
        }
        // ---- online softmax ----
        const float sc = 0.125f;
        #pragma unroll
        for (int i = 0; i < 4; i++) { sa0[i] *= sc; sa1[i] *= sc; }
        float r0m = fmaxf(fmaxf(sa0[0], sa0[1]), fmaxf(sa1[0], sa1[1]));
        float r1m = fmaxf(fmaxf(sa0[2], sa0[3]), fmaxf(sa1[2], sa1[3]));
        r0m = fmaxf(r0m, __shfl_xor_sync(0xffffffffu, r0m, 1));
        r0m = fmaxf(r0m, __shfl_xor_sync(0xffffffffu, r0m, 2));
        r1m = fmaxf(r1m, __shfl_xor_sync(0xffffffffu, r1m, 1));
        r1m = fmaxf(r1m, __shfl_xor_sync(0xffffffffu, r1m, 2));
        const float mn0 = fmaxf(m0, r0m), mn1 = fmaxf(m1, r1m);
        const float al0 = __expf(m0 - mn0), al1 = __expf(m1 - mn1);
        m0 = mn0; m1 = mn1;
        float p[8];
        p[0] = __expf(sa0[0] - mn0); p[1] = __expf(sa0[1] - mn0);
        p[2] = __expf(sa1[0] - mn0); p[3] = __expf(sa1[1] - mn0);
        p[4] = __expf(sa0[2] - mn1); p[5] = __expf(sa0[3] - mn1);
        p[6] = __expf(sa1[2] - mn1); p[7] = __expf(sa1[3] - mn1);
        float rs0 = p[0] + p[1] + p[2] + p[3];
        float rs1 = p[4] + p[5] + p[6] + p[7];
        rs0 += __shfl_xor_sync(0xffffffffu, rs0, 1);
        rs0 += __shfl_xor_sync(0xffffffffu, rs0, 2);
        rs1 += __shfl_xor_sync(0xffffffffu, rs1, 1);
        rs1 += __shfl_xor_sync(0xffffffffu, rs1, 2);
        l0 = l0 * al0 + rs0;
        l1 = l1 * al1 + rs1;
        #pragma unroll
        for (int nt = 0; nt < 8; nt++) {
            oacc[nt][0] *= al0; oacc[nt][1] *= al0;
            oacc[nt][2] *= al1; oacc[nt][3] *= al1;
        }
        // ---- pack P into A-fragments (hi/lo) ----
        // a0=(r,k0-7)=t0c0c1, a1=(r+8,k0-7)=t0c2c3, a2=(r,k8-15)=t1c0c1, a3=t1c2c3
        uint32_t ph[4], pl[4];
        hilo2(p[0], p[1], ph[0], pl[0]);
        hilo2(p[4], p[5], ph[1], pl[1]);
        hilo2(p[2], p[3], ph[2], pl[2]);
        hilo2(p[6], p[7], ph[3], pl[3]);
        // ---- O += P V (3-term) ----
        #pragma unroll
        for (int nt = 0; nt < 4; nt++) {
            const uint32_t vo = (uint32_t)((s0 + ((lane >> 3) & 1) * 8 + (lane & 7)) * AROW
                                           + nt * 32 + (lane >> 4) * 16);
            uint32_t rh[4], rl[4];
            LDSM4T(rh, sVH + vo);
            LDSM4T(rl, sVL + vo);
            uint32_t bh0[2] = {rh[0], rh[1]}, bh1[2] = {rh[2], rh[3]};
            uint32_t bl0[2] = {rl[0], rl[1]}, bl1[2] = {rl[2], rl[3]};
            MMA16816(oacc[2*nt],   ph, bh0);
            MMA16816(oacc[2*nt],   ph, bl0);
            MMA16816(oacc[2*nt],   pl, bh0);
            MMA16816(oacc[2*nt+1], ph, bh1);
            MMA16816(oacc[2*nt+1], ph, bl1);
            MMA16816(oacc[2*nt+1], pl, bh1);
        }
    }

    // ---- normalize + store O as bf16 hi/lo ----
    const float inv0 = 1.f / l0, inv1 = 1.f / l1;
    const int r0 = w * 16 + (lane >> 2);
    const int c0 = (lane & 3) * 2;
    const size_t g0 = base + (size_t)r0 * tstride;
    const size_t g1 = g0 + 8 * tstride;
    #pragma unroll
    for (int nt = 0; nt < 8; nt++) {
        const int col = nt * 8 + c0;
        uint32_t hp, lp;
        hilo2(oacc[nt][0] * inv0, oacc[nt][1] * inv0, hp, lp);
        *reinterpret_cast<uint32_t*>(g_Ohi + g0 + col) = hp;
        *reinterpret_cast<uint32_t*>(g_Olo + g0 + col) = lp;
        hilo2(oacc[nt][2] * inv1, oacc[nt][3] * inv1, hp, lp);
        *reinterpret_cast<uint32_t*>(g_Ohi + g1 + col) = hp;
        *reinterpret_cast<uint32_t*>(g_Olo + g1 + col) = lp;
    }
}

// -------------------------------------------------------------------------------
extern "C" void kernel_launch(void* const* d_in, const int* in_sizes, int n_in,
                              void* d_out, int out_size) {
    const float* x      = (const float*)d_in[0];
    const float* Wq_w   = (const float*)d_in[1];
    const float* Wq_b   = (const float*)d_in[2];
    const float* Wv_w   = (const float*)d_in[3];
    const float* Wv_b   = (const float*)d_in[4];
    const float* Wk     = (const float*)d_in[5];
    const float* bk     = (const float*)d_in[6];
    const float* proj_w = (const float*)d_in[7];
    const float* proj_b = (const float*)d_in[8];
    const int*   cidraw = (const int*)d_in[9];
    float* out = (float*)d_out;

    (void)in_sizes; (void)n_in; (void)out_size;

    void *pXhi, *pXlo, *pQhi, *pQlo, *pKhi, *pKlo, *pVhi, *pVlo, *pOhi, *pOlo;
    cudaGetSymbolAddress(&pXhi, g_Xhi);
    cudaGetSymbolAddress(&pXlo, g_Xlo);
    cudaGetSymbolAddress(&pQhi, g_Qhi);
    cudaGetSymbolAddress(&pQlo, g_Qlo);
    cudaGetSymbolAddress(&pKhi, g_Khi);
    cudaGetSymbolAddress(&pKlo, g_Klo);
    cudaGetSymbolAddress(&pVhi, g_Vhi);
    cudaGetSymbolAddress(&pVlo, g_Vlo);
    cudaGetSymbolAddress(&pOhi, g_Ohi);
    cudaGetSymbolAddress(&pOlo, g_Olo);

    cudaFuncSetAttribute(attn_mma_kernel,
                         cudaFuncAttributeMaxDynamicSharedMemorySize, ASMEM);
    cudaFuncSetAttribute(gemm_mma_kernel<0,1>,
                         cudaFuncAttributeMaxDynamicSharedMemorySize, SMEM_GEMM);
    cudaFuncSetAttribute(gemm_mma_kernel<1,1>,
                         cudaFuncAttributeMaxDynamicSharedMemorySize, SMEM_GEMM);
    cudaFuncSetAttribute(gemm_mma_kernel<0,0>,
                         cudaFuncAttributeMaxDynamicSharedMemorySize, SMEM_GEMM);

    decode_cid_kernel<<<1, 1>>>(cidraw);
    convert_weights_kernel<<<(NW * DD * DD) / 256, 256>>>(Wq_w, Wv_w, proj_w, Wk);
    convert_x_kernel<<<(M_TOTAL * (size_t)DD) / 1024, 256>>>(x);

    dim3 gp(4, M_TOTAL / 128);                 // n-fastest for L2 reuse of A
    gemm_mma_kernel<0,1><<<gp, 256, SMEM_GEMM>>>(
        (const __nv_bfloat16*)pXhi, (const __nv_bfloat16*)pXlo,
        Wq_b, nullptr, nullptr,
        (__nv_bfloat16*)pQhi, (__nv_bfloat16*)pQlo, 0);
    gemm_mma_kernel<0,1><<<gp, 256, SMEM_GEMM>>>(
        (const __nv_bfloat16*)pXhi, (const __nv_bfloat16*)pXlo,
        Wv_b, nullptr, nullptr,
        (__nv_bfloat16*)pVhi, (__nv_bfloat16*)pVlo, 1);

    dim3 gk(4, BT / 128, NNODE);
    gemm_mma_kernel<1,1><<<gk, 256, SMEM_GEMM>>>(
        (const __nv_bfloat16*)pXhi, (const __nv_bfloat16*)pXlo,
        nullptr, bk, nullptr,
        (__nv_bfloat16*)pKhi, (__nv_bfloat16*)pKlo, -1);

    attn_mma_kernel<<<BB * NNODE * HH, 384, ASMEM>>>();   // 4096 blocks

    gemm_mma_kernel<0,0><<<gp, 256, SMEM_GEMM>>>(
        (const __nv_bfloat16*)pOhi, (const __nv_bfloat16*)pOlo,
        proj_b, nullptr, out, nullptr, nullptr, 2);
}

// round 6
// speedup vs baseline: 3.3452x; 1.3669x over previous
#include <cuda_runtime.h>
#include <cuda_fp16.h>
#include <cstdint>

// Problem constants
#define DD    512
#define TT    192
#define NNODE 64
#define BB    8
#define HH    8
#define DHH   64
#define CC    8
#define M_TOTAL (BB*TT*NNODE)   // 98304
#define BT (BB*TT)              // 1536

// ---------------- scratch (allocation-free: __device__ globals) ----------------
__device__ int   g_cid[NNODE];
// activations: fp16 hi/lo split (A-side of GEMMs needs hi+lo; B-side hi only)
__device__ __half g_Xhi[(size_t)M_TOTAL * DD];
__device__ __half g_Xlo[(size_t)M_TOTAL * DD];
__device__ __half g_Qhi[(size_t)M_TOTAL * DD];
__device__ __half g_Qlo[(size_t)M_TOTAL * DD];
__device__ __half g_Khi[(size_t)M_TOTAL * DD];
__device__ __half g_Vhi[(size_t)M_TOTAL * DD];
__device__ __half g_Ohi[(size_t)M_TOTAL * DD];
__device__ __half g_Olo[(size_t)M_TOTAL * DD];
// weights, fp16 (hi only): [0]=Wq, [1]=Wv, [2]=proj (K-major, W[e][d]),
// [3+c] = Wk[c] transposed to K-major
#define NW 11
__device__ __half g_Wh[(size_t)NW * DD * DD];

// ================= PTX helpers (NO arch-'a' instructions: sm_80-safe) ==========
__device__ __forceinline__ uint32_t smem_u32(const void* p) {
    uint32_t a;
    asm("{ .reg .u64 t; cvta.to.shared.u64 t, %1; cvt.u32.u64 %0, t; }" : "=r"(a) : "l"(p));
    return a;
}
#define CP16(saddr, gptr) \
    asm volatile("cp.async.cg.shared.global [%0], [%1], 16;" \
        :: "r"((uint32_t)(saddr)), "l"(gptr))
#define CP_COMMIT() asm volatile("cp.async.commit_group;")
#define CP_WAIT(n)  asm volatile("cp.async.wait_group %0;" :: "n"(n))
#define LDSM4(r, addr) \
    asm volatile("ldmatrix.sync.aligned.m8n8.x4.shared.b16 {%0,%1,%2,%3}, [%4];" \
        : "=r"((r)[0]), "=r"((r)[1]), "=r"((r)[2]), "=r"((r)[3]) : "r"((uint32_t)(addr)))
#define LDSM4T(r, addr) \
    asm volatile("ldmatrix.sync.aligned.m8n8.x4.trans.shared.b16 {%0,%1,%2,%3}, [%4];" \
        : "=r"((r)[0]), "=r"((r)[1]), "=r"((r)[2]), "=r"((r)[3]) : "r"((uint32_t)(addr)))
#define MMAH(d, a, b) \
    asm volatile("mma.sync.aligned.m16n8k16.row.col.f32.f16.f16.f32 " \
        "{%0,%1,%2,%3}, {%4,%5,%6,%7}, {%8,%9}, {%0,%1,%2,%3};" \
        : "+f"((d)[0]), "+f"((d)[1]), "+f"((d)[2]), "+f"((d)[3]) \
        : "r"((a)[0]), "r"((a)[1]), "r"((a)[2]), "r"((a)[3]), \
          "r"((b)[0]), "r"((b)[1]))

__device__ __forceinline__ void hiloh(float v, uint32_t& h, uint32_t& l) {
    __half hb = __float2half_rn(v);
    h = (uint32_t)__half_as_ushort(hb);
    l = (uint32_t)__half_as_ushort(__float2half_rn(v - __half2float(hb)));
}
__device__ __forceinline__ void hilo2h(float v0, float v1, uint32_t& hp, uint32_t& lp) {
    uint32_t h0, l0, h1, l1;
    hiloh(v0, h0, l0); hiloh(v1, h1, l1);
    hp = h0 | (h1 << 16);
    lp = l0 | (l1 << 16);
}

// ---------------- cluster-id decode (handles int64 OR int32 payload) ----------
__global__ void decode_cid_kernel(const int* __restrict__ raw) {
    bool is64 = true;
    for (int i = 0; i < 32; i++) if (raw[2*i + 1] != 0) { is64 = false; break; }
    for (int i = 0; i < NNODE; i++) g_cid[i] = is64 ? raw[2*i] : raw[i];
}

// ---------------- weight conversion prepass: fp32 -> fp16 ---------------------
__global__ __launch_bounds__(256) void convert_weights_kernel(
    const float* __restrict__ Wq, const float* __restrict__ Wv,
    const float* __restrict__ proj, const float* __restrict__ Wk)
{
    int idx = blockIdx.x * 256 + threadIdx.x;
    int w = idx >> 18;
    int rc = idx & 262143;
    float v;
    if (w < 3) {
        const float* src = (w == 0) ? Wq : ((w == 1) ? Wv : proj);
        v = src[rc];
    } else {
        int e = rc >> 9, d = rc & 511;
        v = Wk[(((size_t)(w - 3)) * DD + d) * DD + e];   // transpose to K-major
    }
    g_Wh[idx] = __float2half_rn(v);
}

// ---------------- x conversion prepass: fp32 -> fp16 hi/lo --------------------
__global__ __launch_bounds__(256) void convert_x_kernel(const float* __restrict__ x) {
    size_t i = ((size_t)blockIdx.x * 256 + threadIdx.x) * 4;
    float4 v = *reinterpret_cast<const float4*>(x + i);
    uint32_t hp0, lp0, hp1, lp1;
    hilo2h(v.x, v.y, hp0, lp0);
    hilo2h(v.z, v.w, hp1, lp1);
    uint2 hp, lp;
    hp.x = hp0; hp.y = hp1; lp.x = lp0; lp.y = lp1;
    *reinterpret_cast<uint2*>(g_Xhi + i) = hp;
    *reinterpret_cast<uint2*>(g_Xlo + i) = lp;
}

// ================= mma.sync GEMM: C = A @ W^T + bias ===========================
// 2-term fp16 split: (Ahi + Alo) @ Whi. Block 128x128, 8 warps (2x4),
// warp 64x32, K-chunk 32, 3-stage cp.async pipeline. Row stride 80B.
// OUT: 0 = fp32, 1 = fp16 hi only, 2 = fp16 hi+lo.
#define ROWB 80
#define STG_BYTES (3 * 128 * ROWB)          // 30720 per stage (Ahi, Alo, Bh)
#define SMEM_GEMM (3 * STG_BYTES)           // 92160

template<int GROUPED, int OUT>
__global__ __launch_bounds__(256, 2) void gemm_mma_kernel(
    const __half* __restrict__ Ahi, const __half* __restrict__ Alo,
    const float* __restrict__ bias_plain, const float* __restrict__ bk,
    float* __restrict__ Cf32,
    __half* __restrict__ Chi, __half* __restrict__ Clo,
    int widx)
{
    extern __shared__ char smem[];
    const uint32_t sbase = smem_u32(smem);
    const int tid = threadIdx.x;
    const int lane = tid & 31, wid = tid >> 5;
    const int warp_m = wid & 1;
    const int warp_n = wid >> 1;
    const int n0 = blockIdx.x * 128;
    const int m0 = blockIdx.y * 128;

    int nz = 0, cid = 0;
    const __half* Bh;
    if (GROUPED) {
        nz = blockIdx.z;
        cid = g_cid[nz];
        Bh = g_Wh + (size_t)(3 + cid) * DD * DD;
    } else {
        Bh = g_Wh + (size_t)widx * DD * DD;
    }

    float acc[4][4][4];
    #pragma unroll
    for (int a = 0; a < 4; a++)
        #pragma unroll
        for (int b = 0; b < 4; b++)
            #pragma unroll
            for (int c = 0; c < 4; c++) acc[a][b][c] = 0.f;

    auto load_chunk = [&](int kc) {
        const int k0 = kc * 32;
        const uint32_t st = sbase + (kc % 3) * STG_BYTES;
        #pragma unroll
        for (int i = 0; i < 2; i++) {
            const int u = tid * 2 + i;
            const int row = u >> 2, c = u & 3;
            const uint32_t so = (uint32_t)(row * ROWB + c * 16);
            size_t arow = GROUPED ? ((size_t)(m0 + row) * NNODE + nz)
                                  : (size_t)(m0 + row);
            CP16(st + so, Ahi + arow * DD + k0 + c * 8);
            CP16(st + 10240 + so, Alo + arow * DD + k0 + c * 8);
            CP16(st + 20480 + so, Bh + (size_t)(n0 + row) * DD + k0 + c * 8);
        }
    };

    load_chunk(0); CP_COMMIT();
    load_chunk(1); CP_COMMIT();

    for (int kc = 0; kc < 16; kc++) {
        if (kc == 15) { CP_WAIT(0); } else { CP_WAIT(1); }
        __syncthreads();
        if (kc + 2 < 16) { load_chunk(kc + 2); CP_COMMIT(); }

        const uint32_t sa  = sbase + (kc % 3) * STG_BYTES;
        const uint32_t sal = sa + 10240;
        const uint32_t sb  = sa + 20480;

        #pragma unroll
        for (int ks = 0; ks < 2; ks++) {
            uint32_t ahi[4][4], alo[4][4], bh[4][2];
            #pragma unroll
            for (int mi = 0; mi < 4; mi++) {
                const uint32_t ao = (uint32_t)((warp_m * 64 + mi * 16 + (lane & 15)) * ROWB
                                               + ks * 32 + (lane >> 4) * 16);
                LDSM4(ahi[mi], sa + ao);
                LDSM4(alo[mi], sal + ao);
            }
            #pragma unroll
            for (int nb = 0; nb < 2; nb++) {
                const uint32_t bo = (uint32_t)((warp_n * 32 + nb * 16 + ((lane >> 4) << 3)
                                                + (lane & 7)) * ROWB
                                               + ks * 32 + ((lane >> 3) & 1) * 16);
                uint32_t r[4];
                LDSM4(r, sb + bo);
                bh[nb*2][0] = r[0]; bh[nb*2][1] = r[1];
                bh[nb*2+1][0] = r[2]; bh[nb*2+1][1] = r[3];
            }
            #pragma unroll
            for (int mi = 0; mi < 4; mi++)
                #pragma unroll
                for (int nj = 0; nj < 4; nj++) {
                    MMAH(acc[mi][nj], ahi[mi], bh[nj]);
                    MMAH(acc[mi][nj], alo[mi], bh[nj]);
                }
        }
    }

    // epilogue
    const float* bias = GROUPED ? (bk + (size_t)cid * DD) : bias_plain;
    #pragma unroll
    for (int mi = 0; mi < 4; mi++) {
        #pragma unroll
        for (int nj = 0; nj < 4; nj++) {
            const int col = n0 + warp_n * 32 + nj * 8 + (lane & 3) * 2;
            const float b0 = bias[col], b1 = bias[col + 1];
            const int r0 = m0 + warp_m * 64 + mi * 16 + (lane >> 2);
            const size_t ro0 = GROUPED ? ((size_t)r0 * NNODE + nz) : (size_t)r0;
            const size_t ro1 = GROUPED ? ((size_t)(r0 + 8) * NNODE + nz) : (size_t)(r0 + 8);
            float v0 = acc[mi][nj][0] + b0, v1 = acc[mi][nj][1] + b1;
            float v2 = acc[mi][nj][2] + b0, v3 = acc[mi][nj][3] + b1;
            if (OUT == 2) {
                uint32_t hp, lp;
                hilo2h(v0, v1, hp, lp);
                *reinterpret_cast<uint32_t*>(Chi + ro0 * DD + col) = hp;
                *reinterpret_cast<uint32_t*>(Clo + ro0 * DD + col) = lp;
                hilo2h(v2, v3, hp, lp);
                *reinterpret_cast<uint32_t*>(Chi + ro1 * DD + col) = hp;
                *reinterpret_cast<uint32_t*>(Clo + ro1 * DD + col) = lp;
            } else if (OUT == 1) {
                __half2 h0; h0.x = __float2half_rn(v0); h0.y = __float2half_rn(v1);
                __half2 h1; h1.x = __float2half_rn(v2); h1.y = __float2half_rn(v3);
                *reinterpret_cast<__half2*>(Chi + ro0 * DD + col) = h0;
                *reinterpret_cast<__half2*>(Chi + ro1 * DD + col) = h1;
            } else {
                float2 w0; w0.x = v0; w0.y = v1;
                float2 w1; w1.x = v2; w1.y = v3;
                *reinterpret_cast<float2*>(Cf32 + ro0 * DD + col) = w0;
                *reinterpret_cast<float2*>(Cf32 + ro1 * DD + col) = w1;
            }
        }
    }
}

// ================= tensor-core attention ======================================
// Block = (b,n,h), 384 threads (12 warps); warp w owns query rows [16w,16w+16).
// smem: Qhi, Qlo, Khi, Vhi (fp16), row stride 144B.
// S = (Qhi+Qlo)·Khi^T;  O = (Phi+Plo)·Vhi.  2-term fp16 splits.
#define AROW 144
#define ATEN (192 * AROW)            // 27648 per sub-tensor
#define ASMEM (4 * ATEN)             // 110592

__global__ __launch_bounds__(384, 1) void attn_mma_kernel() {
    extern __shared__ char smem[];
    const uint32_t sbase = smem_u32(smem);
    const int tid = threadIdx.x;
    const int lane = tid & 31, w = tid >> 5;

    const int bx = blockIdx.x;
    const int h = bx & 7;
    const int n = (bx >> 3) & 63;
    const int b = bx >> 9;
    const size_t base = ((size_t)b * TT * NNODE + n) * DD + h * DHH;
    const size_t tstride = (size_t)NNODE * DD;   // 32768

    // ---- stage Q hi/lo, K hi, V hi into smem ----
    {
        #pragma unroll
        for (int ti = 0; ti < 4; ti++) {
            const __half* tp = (ti == 0) ? (g_Qhi + base) : (ti == 1) ? (g_Qlo + base)
                             : (ti == 2) ? (g_Khi + base) : (g_Vhi + base);
            char* sp = smem + ti * ATEN;
            #pragma unroll
            for (int i = 0; i < 4; i++) {
                const int c = tid + i * 384;        // 0..1535
                const int r = c >> 3, o = c & 7;
                *reinterpret_cast<uint4*>(sp + r * AROW + o * 16) =
                    *reinterpret_cast<const uint4*>(tp + (size_t)r * tstride + o * 8);
            }
        }
    }
    __syncthreads();

    const uint32_t sQH = sbase, sQL = sbase + ATEN;
    const uint32_t sKH = sbase + 2 * ATEN;
    const uint32_t sVH = sbase + 3 * ATEN;

    // ---- preload Q fragments (16 rows x 64 k, hi+lo) ----
    uint32_t qh[4][4], ql[4][4];
    {
        const int qrow = w * 16 + (lane & 15);
        #pragma unroll
        for (int kt = 0; kt < 4; kt++) {
            const uint32_t ao = (uint32_t)(qrow * AROW + kt * 32 + (lane >> 4) * 16);
            LDSM4(qh[kt], sQH + ao);
            LDSM4(ql[kt], sQL + ao);
        }
    }

    float oacc[8][4];
    #pragma unroll
    for (int i = 0; i < 8; i++)
        #pragma unroll
        for (int j = 0; j < 4; j++) oacc[i][j] = 0.f;
    float m0 = -1e30f, m1 = -1e30f, l0 = 0.f, l1 = 0.f;

    for (int s0 = 0; s0 < TT; s0 += 16) {
        // ---- S = Q K^T (2-term) ----
        float sa0[4] = {0.f, 0.f, 0.f, 0.f};
        float sa1[4] = {0.f, 0.f, 0.f, 0.f};
        #pragma unroll
        for (int kt = 0; kt < 4; kt++) {
            const uint32_t bo = (uint32_t)((s0 + ((lane >> 4) << 3) + (lane & 7)) * AROW
                                           + kt * 32 + ((lane >> 3) & 1) * 16);
            uint32_t rh[4];
            LDSM4(rh, sKH + bo);
            uint32_t bh0[2] = {rh[0], rh[1]}, bh1[2] = {rh[2], rh[3]};
            MMAH(sa0, qh[kt], bh0);
            MMAH(sa0, ql[kt], bh0);
            MMAH(sa1, qh[kt], bh1);
            MMAH(sa1, ql[kt], bh1);
        }
        // ---- online softmax ----
        const float sc = 0.125f;
        #pragma unroll
        for (int i = 0; i < 4; i++) { sa0[i] *= sc; sa1[i] *= sc; }
        float r0m = fmaxf(fmaxf(sa0[0], sa0[1]), fmaxf(sa1[0], sa1[1]));
        float r1m = fmaxf(fmaxf(sa0[2], sa0[3]), fmaxf(sa1[2], sa1[3]));
        r0m = fmaxf(r0m, __shfl_xor_sync(0xffffffffu, r0m, 1));
        r0m = fmaxf(r0m, __shfl_xor_sync(0xffffffffu, r0m, 2));
        r1m = fmaxf(r1m, __shfl_xor_sync(0xffffffffu, r1m, 1));
        r1m = fmaxf(r1m, __shfl_xor_sync(0xffffffffu, r1m, 2));
        const float mn0 = fmaxf(m0, r0m), mn1 = fmaxf(m1, r1m);
        const float al0 = __expf(m0 - mn0), al1 = __expf(m1 - mn1);
        m0 = mn0; m1 = mn1;
        float p[8];
        p[0] = __expf(sa0[0] - mn0); p[1] = __expf(sa0[1] - mn0);
        p[2] = __expf(sa1[0] - mn0); p[3] = __expf(sa1[1] - mn0);
        p[4] = __expf(sa0[2] - mn1); p[5] = __expf(sa0[3] - mn1);
        p[6] = __expf(sa1[2] - mn1); p[7] = __expf(sa1[3] - mn1);
        float rs0 = p[0] + p[1] + p[2] + p[3];
        float rs1 = p[4] + p[5] + p[6] + p[7];
        rs0 += __shfl_xor_sync(0xffffffffu, rs0, 1);
        rs0 += __shfl_xor_sync(0xffffffffu, rs0, 2);
        rs1 += __shfl_xor_sync(0xffffffffu, rs1, 1);
        rs1 += __shfl_xor_sync(0xffffffffu, rs1, 2);
        l0 = l0 * al0 + rs0;
        l1 = l1 * al1 + rs1;
        #pragma unroll
        for (int nt = 0; nt < 8; nt++) {
            oacc[nt][0] *= al0; oacc[nt][1] *= al0;
            oacc[nt][2] *= al1; oacc[nt][3] *= al1;
        }
        // ---- pack P into A-fragments (fp16 hi/lo) ----
        // a0=(r,k0-7)=t0c0c1, a1=(r+8,k0-7)=t0c2c3, a2=(r,k8-15)=t1c0c1, a3=t1c2c3
        uint32_t ph[4], pl[4];
        hilo2h(p[0], p[1], ph[0], pl[0]);
        hilo2h(p[4], p[5], ph[1], pl[1]);
        hilo2h(p[2], p[3], ph[2], pl[2]);
        hilo2h(p[6], p[7], ph[3], pl[3]);
        // ---- O += P V (2-term) ----
        #pragma unroll
        for (int nt = 0; nt < 4; nt++) {
            const uint32_t vo = (uint32_t)((s0 + ((lane >> 3) & 1) * 8 + (lane & 7)) * AROW
                                           + nt * 32 + (lane >> 4) * 16);
            uint32_t rh[4];
            LDSM4T(rh, sVH + vo);
            uint32_t bh0[2] = {rh[0], rh[1]}, bh1[2] = {rh[2], rh[3]};
            MMAH(oacc[2*nt],   ph, bh0);
            MMAH(oacc[2*nt],   pl, bh0);
            MMAH(oacc[2*nt+1], ph, bh1);
            MMAH(oacc[2*nt+1], pl, bh1);
        }
    }

    // ---- normalize + store O as fp16 hi/lo ----
    const float inv0 = 1.f / l0, inv1 = 1.f / l1;
    const int r0 = w * 16 + (lane >> 2);
    const int c0 = (lane & 3) * 2;
    const size_t g0 = base + (size_t)r0 * tstride;
    const size_t g1 = g0 + 8 * tstride;
    #pragma unroll
    for (int nt = 0; nt < 8; nt++) {
        const int col = nt * 8 + c0;
        uint32_t hp, lp;
        hilo2h(oacc[nt][0] * inv0, oacc[nt][1] * inv0, hp, lp);
        *reinterpret_cast<uint32_t*>(g_Ohi + g0 + col) = hp;
        *reinterpret_cast<uint32_t*>(g_Olo + g0 + col) = lp;
        hilo2h(oacc[nt][2] * inv1, oacc[nt][3] * inv1, hp, lp);
        *reinterpret_cast<uint32_t*>(g_Ohi + g1 + col) = hp;
        *reinterpret_cast<uint32_t*>(g_Olo + g1 + col) = lp;
    }
}

// -------------------------------------------------------------------------------
extern "C" void kernel_launch(void* const* d_in, const int* in_sizes, int n_in,
                              void* d_out, int out_size) {
    const float* x      = (const float*)d_in[0];
    const float* Wq_w   = (const float*)d_in[1];
    const float* Wq_b   = (const float*)d_in[2];
    const float* Wv_w   = (const float*)d_in[3];
    const float* Wv_b   = (const float*)d_in[4];
    const float* Wk     = (const float*)d_in[5];
    const float* bk     = (const float*)d_in[6];
    const float* proj_w = (const float*)d_in[7];
    const float* proj_b = (const float*)d_in[8];
    const int*   cidraw = (const int*)d_in[9];
    float* out = (float*)d_out;

    (void)in_sizes; (void)n_in; (void)out_size;

    void *pXhi, *pXlo, *pQhi, *pQlo, *pKhi, *pVhi, *pOhi, *pOlo;
    cudaGetSymbolAddress(&pXhi, g_Xhi);
    cudaGetSymbolAddress(&pXlo, g_Xlo);
    cudaGetSymbolAddress(&pQhi, g_Qhi);
    cudaGetSymbolAddress(&pQlo, g_Qlo);
    cudaGetSymbolAddress(&pKhi, g_Khi);
    cudaGetSymbolAddress(&pVhi, g_Vhi);
    cudaGetSymbolAddress(&pOhi, g_Ohi);
    cudaGetSymbolAddress(&pOlo, g_Olo);

    cudaFuncSetAttribute(attn_mma_kernel,
                         cudaFuncAttributeMaxDynamicSharedMemorySize, ASMEM);
    cudaFuncSetAttribute(gemm_mma_kernel<0,2>,
                         cudaFuncAttributeMaxDynamicSharedMemorySize, SMEM_GEMM);
    cudaFuncSetAttribute(gemm_mma_kernel<0,1>,
                         cudaFuncAttributeMaxDynamicSharedMemorySize, SMEM_GEMM);
    cudaFuncSetAttribute(gemm_mma_kernel<1,1>,
                         cudaFuncAttributeMaxDynamicSharedMemorySize, SMEM_GEMM);
    cudaFuncSetAttribute(gemm_mma_kernel<0,0>,
                         cudaFuncAttributeMaxDynamicSharedMemorySize, SMEM_GEMM);

    decode_cid_kernel<<<1, 1>>>(cidraw);
    convert_weights_kernel<<<(NW * DD * DD) / 256, 256>>>(Wq_w, Wv_w, proj_w, Wk);
    convert_x_kernel<<<(M_TOTAL * (size_t)DD) / 1024, 256>>>(x);

    dim3 gp(4, M_TOTAL / 128);                 // n-fastest for L2 reuse of A
    gemm_mma_kernel<0,2><<<gp, 256, SMEM_GEMM>>>(
        (const __half*)pXhi, (const __half*)pXlo,
        Wq_b, nullptr, nullptr,
        (__half*)pQhi, (__half*)pQlo, 0);
    gemm_mma_kernel<0,1><<<gp, 256, SMEM_GEMM>>>(
        (const __half*)pXhi, (const __half*)pXlo,
        Wv_b, nullptr, nullptr,
        (__half*)pVhi, nullptr, 1);

    dim3 gk(4, BT / 128, NNODE);
    gemm_mma_kernel<1,1><<<gk, 256, SMEM_GEMM>>>(
        (const __half*)pXhi, (const __half*)pXlo,
        nullptr, bk, nullptr,
        (__half*)pKhi, nullptr, -1);

    attn_mma_kernel<<<BB * NNODE * HH, 384, ASMEM>>>();   // 4096 blocks

    gemm_mma_kernel<0,0><<<gp, 256, SMEM_GEMM>>>(
        (const __half*)pOhi, (const __half*)pOlo,
        proj_b, nullptr, out, nullptr, nullptr, 2);
}

// round 8
// speedup vs baseline: 3.3844x; 1.0117x over previous
#include <cuda_runtime.h>
#include <cuda_fp16.h>
#include <cstdint>

// Problem constants
#define DD    512
#define TT    192
#define NNODE 64
#define BB    8
#define HH    8
#define DHH   64
#define CC    8
#define M_TOTAL (BB*TT*NNODE)   // 98304
#define BT (BB*TT)              // 1536

// ---------------- scratch (allocation-free: __device__ globals) ----------------
__device__ int   g_cid[NNODE];
// activations: fp16 hi/lo split (A-side of GEMMs needs hi+lo; B-side hi only)
__device__ __half g_Xhi[(size_t)M_TOTAL * DD];
__device__ __half g_Xlo[(size_t)M_TOTAL * DD];
__device__ __half g_Qhi[(size_t)M_TOTAL * DD];
__device__ __half g_Qlo[(size_t)M_TOTAL * DD];
__device__ __half g_Khi[(size_t)M_TOTAL * DD];
__device__ __half g_Vhi[(size_t)M_TOTAL * DD];
__device__ __half g_Ohi[(size_t)M_TOTAL * DD];
__device__ __half g_Olo[(size_t)M_TOTAL * DD];
// weights, fp16 (hi only): [0]=Wq, [1]=Wv, [2]=proj (K-major, W[e][d]),
// [3+c] = Wk[c] transposed to K-major
#define NW 11
__device__ __half g_Wh[(size_t)NW * DD * DD];

// ================= PTX helpers (NO arch-'a' instructions: sm_80-safe) ==========
__device__ __forceinline__ uint32_t smem_u32(const void* p) {
    uint32_t a;
    asm("{ .reg .u64 t; cvta.to.shared.u64 t, %1; cvt.u32.u64 %0, t; }" : "=r"(a) : "l"(p));
    return a;
}
#define CP16(saddr, gptr) \
    asm volatile("cp.async.cg.shared.global [%0], [%1], 16;" \
        :: "r"((uint32_t)(saddr)), "l"(gptr))
#define CP_COMMIT() asm volatile("cp.async.commit_group;")
#define CP_WAIT(n)  asm volatile("cp.async.wait_group %0;" :: "n"(n))
#define LDSM4(r, addr) \
    asm volatile("ldmatrix.sync.aligned.m8n8.x4.shared.b16 {%0,%1,%2,%3}, [%4];" \
        : "=r"((r)[0]), "=r"((r)[1]), "=r"((r)[2]), "=r"((r)[3]) : "r"((uint32_t)(addr)))
#define LDSM4T(r, addr) \
    asm volatile("ldmatrix.sync.aligned.m8n8.x4.trans.shared.b16 {%0,%1,%2,%3}, [%4];" \
        : "=r"((r)[0]), "=r"((r)[1]), "=r"((r)[2]), "=r"((r)[3]) : "r"((uint32_t)(addr)))
#define MMAH(d, a, b) \
    asm volatile("mma.sync.aligned.m16n8k16.row.col.f32.f16.f16.f32 " \
        "{%0,%1,%2,%3}, {%4,%5,%6,%7}, {%8,%9}, {%0,%1,%2,%3};" \
        : "+f"((d)[0]), "+f"((d)[1]), "+f"((d)[2]), "+f"((d)[3]) \
        : "r"((a)[0]), "r"((a)[1]), "r"((a)[2]), "r"((a)[3]), \
          "r"((b)[0]), "r"((b)[1]))

__device__ __forceinline__ void hiloh(float v, uint32_t& h, uint32_t& l) {
    __half hb = __float2half_rn(v);
    h = (uint32_t)__half_as_ushort(hb);
    l = (uint32_t)__half_as_ushort(__float2half_rn(v - __half2float(hb)));
}
__device__ __forceinline__ void hilo2h(float v0, float v1, uint32_t& hp, uint32_t& lp) {
    uint32_t h0, l0, h1, l1;
    hiloh(v0, h0, l0); hiloh(v1, h1, l1);
    hp = h0 | (h1 << 16);
    lp = l0 | (l1 << 16);
}

// ---------------- cluster-id decode (handles int64 OR int32 payload) ----------
__global__ void decode_cid_kernel(const int* __restrict__ raw) {
    bool is64 = true;
    for (int i = 0; i < 32; i++) if (raw[2*i + 1] != 0) { is64 = false; break; }
    for (int i = 0; i < NNODE; i++) g_cid[i] = is64 ? raw[2*i] : raw[i];
}

// ---------------- weight conversion prepass: fp32 -> fp16 ---------------------
__global__ __launch_bounds__(256) void convert_weights_kernel(
    const float* __restrict__ Wq, const float* __restrict__ Wv,
    const float* __restrict__ proj, const float* __restrict__ Wk)
{
    int idx = blockIdx.x * 256 + threadIdx.x;
    int w = idx >> 18;
    int rc = idx & 262143;
    float v;
    if (w < 3) {
        const float* src = (w == 0) ? Wq : ((w == 1) ? Wv : proj);
        v = src[rc];
    } else {
        int e = rc >> 9, d = rc & 511;
        v = Wk[(((size_t)(w - 3)) * DD + d) * DD + e];   // transpose to K-major
    }
    g_Wh[idx] = __float2half_rn(v);
}

// ---------------- x conversion prepass: fp32 -> fp16 hi/lo --------------------
__global__ __launch_bounds__(256) void convert_x_kernel(const float* __restrict__ x) {
    size_t i = ((size_t)blockIdx.x * 256 + threadIdx.x) * 4;
    float4 v = *reinterpret_cast<const float4*>(x + i);
    uint32_t hp0, lp0, hp1, lp1;
    hilo2h(v.x, v.y, hp0, lp0);
    hilo2h(v.z, v.w, hp1, lp1);
    uint2 hp, lp;
    hp.x = hp0; hp.y = hp1; lp.x = lp0; lp.y = lp1;
    *reinterpret_cast<uint2*>(g_Xhi + i) = hp;
    *reinterpret_cast<uint2*>(g_Xlo + i) = lp;
}

// ================= mma.sync GEMM: C = A @ W^T + bias ===========================
// 2-term fp16 split: (Ahi + Alo) @ Whi. Block 128x128, 8 warps (4x2),
// warp tile 32x64, K-chunk 32, 3-stage cp.async pipeline. Row stride 80B.
// OUT: 0 = fp32, 1 = fp16 hi only, 2 = fp16 hi+lo.
#define ROWB 80
#define STG_BYTES (3 * 128 * ROWB)          // 30720 per stage (Ahi, Alo, Bh)
#define SMEM_GEMM (3 * STG_BYTES)           // 92160

template<int GROUPED, int OUT>
__global__ __launch_bounds__(256, 2) void gemm_mma_kernel(
    const __half* __restrict__ Ahi, const __half* __restrict__ Alo,
    const float* __restrict__ bias_plain, const float* __restrict__ bk,
    float* __restrict__ Cf32,
    __half* __restrict__ Chi, __half* __restrict__ Clo,
    int widx)
{
    extern __shared__ char smem[];
    const uint32_t sbase = smem_u32(smem);
    const int tid = threadIdx.x;
    const int lane = tid & 31, wid = tid >> 5;
    const int warp_m = wid & 3;       // 4 m-tiles of 32 rows
    const int warp_n = wid >> 2;      // 2 n-tiles of 64 cols
    const int n0 = blockIdx.x * 128;
    const int m0 = blockIdx.y * 128;

    int nz = 0, cid = 0;
    const __half* Bh;
    if (GROUPED) {
        nz = blockIdx.z;
        cid = g_cid[nz];
        Bh = g_Wh + (size_t)(3 + cid) * DD * DD;
    } else {
        Bh = g_Wh + (size_t)widx * DD * DD;
    }

    float acc[2][8][4];
    #pragma unroll
    for (int a = 0; a < 2; a++)
        #pragma unroll
        for (int b = 0; b < 8; b++)
            #pragma unroll
            for (int c = 0; c < 4; c++) acc[a][b][c] = 0.f;

    auto load_chunk = [&](int kc) {
        const int k0 = kc * 32;
        const uint32_t st = sbase + (kc % 3) * STG_BYTES;
        #pragma unroll
        for (int i = 0; i < 2; i++) {
            const int u = tid * 2 + i;
            const int row = u >> 2, c = u & 3;
            const uint32_t so = (uint32_t)(row * ROWB + c * 16);
            size_t arow = GROUPED ? ((size_t)(m0 + row) * NNODE + nz)
                                  : (size_t)(m0 + row);
            CP16(st + so, Ahi + arow * DD + k0 + c * 8);
            CP16(st + 10240 + so, Alo + arow * DD + k0 + c * 8);
            CP16(st + 20480 + so, Bh + (size_t)(n0 + row) * DD + k0 + c * 8);
        }
    };

    load_chunk(0); CP_COMMIT();
    load_chunk(1); CP_COMMIT();

    for (int kc = 0; kc < 16; kc++) {
        if (kc == 15) { CP_WAIT(0); } else { CP_WAIT(1); }
        __syncthreads();
        if (kc + 2 < 16) { load_chunk(kc + 2); CP_COMMIT(); }

        const uint32_t sa  = sbase + (kc % 3) * STG_BYTES;
        const uint32_t sal = sa + 10240;
        const uint32_t sb  = sa + 20480;

        #pragma unroll
        for (int ks = 0; ks < 2; ks++) {
            uint32_t ahi[2][4], alo[2][4], bh[8][2];
            // B fragments first: 4 LDSM4 cover 64 cols x 16 k
            #pragma unroll
            for (int nb = 0; nb < 4; nb++) {
                const uint32_t bo = (uint32_t)((warp_n * 64 + nb * 16 + ((lane >> 4) << 3)
                                                + (lane & 7)) * ROWB
                                               + ks * 32 + ((lane >> 3) & 1) * 16);
                uint32_t r[4];
                LDSM4(r, sb + bo);
                bh[nb*2][0] = r[0]; bh[nb*2][1] = r[1];
                bh[nb*2+1][0] = r[2]; bh[nb*2+1][1] = r[3];
            }
            // A fragments: 2 m16 tiles, hi + lo
            #pragma unroll
            for (int mi = 0; mi < 2; mi++) {
                const uint32_t ao = (uint32_t)((warp_m * 32 + mi * 16 + (lane & 15)) * ROWB
                                               + ks * 32 + (lane >> 4) * 16);
                LDSM4(ahi[mi], sa + ao);
                LDSM4(alo[mi], sal + ao);
            }
            #pragma unroll
            for (int mi = 0; mi < 2; mi++)
                #pragma unroll
                for (int nj = 0; nj < 8; nj++) {
                    MMAH(acc[mi][nj], ahi[mi], bh[nj]);
                    MMAH(acc[mi][nj], alo[mi], bh[nj]);
                }
        }
    }

    // epilogue
    const float* bias = GROUPED ? (bk + (size_t)cid * DD) : bias_plain;
    #pragma unroll
    for (int mi = 0; mi < 2; mi++) {
        #pragma unroll
        for (int nj = 0; nj < 8; nj++) {
            const int col = n0 + warp_n * 64 + nj * 8 + (lane & 3) * 2;
            const float b0 = bias[col], b1 = bias[col + 1];
            const int r0 = m0 + warp_m * 32 + mi * 16 + (lane >> 2);
            const size_t ro0 = GROUPED ? ((size_t)r0 * NNODE + nz) : (size_t)r0;
            const size_t ro1 = GROUPED ? ((size_t)(r0 + 8) * NNODE + nz) : (size_t)(r0 + 8);
            float v0 = acc[mi][nj][0] + b0, v1 = acc[mi][nj][1] + b1;
            float v2 = acc[mi][nj][2] + b0, v3 = acc[mi][nj][3] + b1;
            if (OUT == 2) {
                uint32_t hp, lp;
                hilo2h(v0, v1, hp, lp);
                *reinterpret_cast<uint32_t*>(Chi + ro0 * DD + col) = hp;
                *reinterpret_cast<uint32_t*>(Clo + ro0 * DD + col) = lp;
                hilo2h(v2, v3, hp, lp);
                *reinterpret_cast<uint32_t*>(Chi + ro1 * DD + col) = hp;
                *reinterpret_cast<uint32_t*>(Clo + ro1 * DD + col) = lp;
            } else if (OUT == 1) {
                __half2 h0; h0.x = __float2half_rn(v0); h0.y = __float2half_rn(v1);
                __half2 h1; h1.x = __float2half_rn(v2); h1.y = __float2half_rn(v3);
                *reinterpret_cast<__half2*>(Chi + ro0 * DD + col) = h0;
                *reinterpret_cast<__half2*>(Chi + ro1 * DD + col) = h1;
            } else {
                float2 w0; w0.x = v0; w0.y = v1;
                float2 w1; w1.x = v2; w1.y = v3;
                *reinterpret_cast<float2*>(Cf32 + ro0 * DD + col) = w0;
                *reinterpret_cast<float2*>(Cf32 + ro1 * DD + col) = w1;
            }
        }
    }
}

// ================= tensor-core attention ======================================
// Block = (b,n,h), 384 threads (12 warps); warp w owns query rows [16w,16w+16).
// smem: Qhi, Qlo, Khi, Vhi (fp16), row stride 144B.
// S = (Qhi+Qlo)·Khi^T;  O = (Phi+Plo)·Vhi.  2-term fp16 splits.
#define AROW 144
#define ATEN (192 * AROW)            // 27648 per sub-tensor
#define ASMEM (4 * ATEN)             // 110592

__global__ __launch_bounds__(384, 1) void attn_mma_kernel() {
    extern __shared__ char smem[];
    const uint32_t sbase = smem_u32(smem);
    const int tid = threadIdx.x;
    const int lane = tid & 31, w = tid >> 5;

    const int bx = blockIdx.x;
    const int h = bx & 7;
    const int n = (bx >> 3) & 63;
    const int b = bx >> 9;
    const size_t base = ((size_t)b * TT * NNODE + n) * DD + h * DHH;
    const size_t tstride = (size_t)NNODE * DD;   // 32768

    // ---- stage Q hi/lo, K hi, V hi into smem ----
    {
        #pragma unroll
        for (int ti = 0; ti < 4; ti++) {
            const __half* tp = (ti == 0) ? (g_Qhi + base) : (ti == 1) ? (g_Qlo + base)
                             : (ti == 2) ? (g_Khi + base) : (g_Vhi + base);
            char* sp = smem + ti * ATEN;
            #pragma unroll
            for (int i = 0; i < 4; i++) {
                const int c = tid + i * 384;        // 0..1535
                const int r = c >> 3, o = c & 7;
                *reinterpret_cast<uint4*>(sp + r * AROW + o * 16) =
                    *reinterpret_cast<const uint4*>(tp + (size_t)r * tstride + o * 8);
            }
        }
    }
    __syncthreads();

    const uint32_t sQH = sbase, sQL = sbase + ATEN;
    const uint32_t sKH = sbase + 2 * ATEN;
    const uint32_t sVH = sbase + 3 * ATEN;

    // ---- preload Q fragments (16 rows x 64 k, hi+lo) ----
    uint32_t qh[4][4], ql[4][4];
    {
        const int qrow = w * 16 + (lane & 15);
        #pragma unroll
        for (int kt = 0; kt < 4; kt++) {
            const uint32_t ao = (uint32_t)(qrow * AROW + kt * 32 + (lane >> 4) * 16);
            LDSM4(qh[kt], sQH + ao);
            LDSM4(ql[kt], sQL + ao);
        }
    }

    float oacc[8][4];
    #pragma unroll
    for (int i = 0; i < 8; i++)
        #pragma unroll
        for (int j = 0; j < 4; j++) oacc[i][j] = 0.f;
    float m0 = -1e30f, m1 = -1e30f, l0 = 0.f, l1 = 0.f;

    for (int s0 = 0; s0 < TT; s0 += 16) {
        // ---- S = Q K^T (2-term) ----
        float sa0[4] = {0.f, 0.f, 0.f, 0.f};
        float sa1[4] = {0.f, 0.f, 0.f, 0.f};
        #pragma unroll
        for (int kt = 0; kt < 4; kt++) {
            const uint32_t bo = (uint32_t)((s0 + ((lane >> 4) << 3) + (lane & 7)) * AROW
                                           + kt * 32 + ((lane >> 3) & 1) * 16);
            uint32_t rh[4];
            LDSM4(rh, sKH + bo);
            uint32_t bh0[2] = {rh[0], rh[1]}, bh1[2] = {rh[2], rh[3]};
            MMAH(sa0, qh[kt], bh0);
            MMAH(sa0, ql[kt], bh0);
            MMAH(sa1, qh[kt], bh1);
            MMAH(sa1, ql[kt], bh1);
        }
        // ---- online softmax ----
        const float sc = 0.125f;
        #pragma unroll
        for (int i = 0; i < 4; i++) { sa0[i] *= sc; sa1[i] *= sc; }
        float r0m = fmaxf(fmaxf(sa0[0], sa0[1]), fmaxf(sa1[0], sa1[1]));
        float r1m = fmaxf(fmaxf(sa0[2], sa0[3]), fmaxf(sa1[2], sa1[3]));
        r0m = fmaxf(r0m, __shfl_xor_sync(0xffffffffu, r0m, 1));
        r0m = fmaxf(r0m, __shfl_xor_sync(0xffffffffu, r0m, 2));
        r1m = fmaxf(r1m, __shfl_xor_sync(0xffffffffu, r1m, 1));
        r1m = fmaxf(r1m, __shfl_xor_sync(0xffffffffu, r1m, 2));
        const float mn0 = fmaxf(m0, r0m), mn1 = fmaxf(m1, r1m);
        const float al0 = __expf(m0 - mn0), al1 = __expf(m1 - mn1);
        m0 = mn0; m1 = mn1;
        float p[8];
        p[0] = __expf(sa0[0] - mn0); p[1] = __expf(sa0[1] - mn0);
        p[2] = __expf(sa1[0] - mn0); p[3] = __expf(sa1[1] - mn0);
        p[4] = __expf(sa0[2] - mn1); p[5] = __expf(sa0[3] - mn1);
        p[6] = __expf(sa1[2] - mn1); p[7] = __expf(sa1[3] - mn1);
        float rs0 = p[0] + p[1] + p[2] + p[3];
        float rs1 = p[4] + p[5] + p[6] + p[7];
        rs0 += __shfl_xor_sync(0xffffffffu, rs0, 1);
        rs0 += __shfl_xor_sync(0xffffffffu, rs0, 2);
        rs1 += __shfl_xor_sync(0xffffffffu, rs1, 1);
        rs1 += __shfl_xor_sync(0xffffffffu, rs1, 2);
        l0 = l0 * al0 + rs0;
        l1 = l1 * al1 + rs1;
        #pragma unroll
        for (int nt = 0; nt < 8; nt++) {
            oacc[nt][0] *= al0; oacc[nt][1] *= al0;
            oacc[nt][2] *= al1; oacc[nt][3] *= al1;
        }
        // ---- pack P into A-fragments (fp16 hi/lo) ----
        uint32_t ph[4], pl[4];
        hilo2h(p[0], p[1], ph[0], pl[0]);
        hilo2h(p[4], p[5], ph[1], pl[1]);
        hilo2h(p[2], p[3], ph[2], pl[2]);
        hilo2h(p[6], p[7], ph[3], pl[3]);
        // ---- O += P V (2-term) ----
        #pragma unroll
        for (int nt = 0; nt < 4; nt++) {
            const uint32_t vo = (uint32_t)((s0 + ((lane >> 3) & 1) * 8 + (lane & 7)) * AROW
                                           + nt * 32 + (lane >> 4) * 16);
            uint32_t rh[4];
            LDSM4T(rh, sVH + vo);
            uint32_t bh0[2] = {rh[0], rh[1]}, bh1[2] = {rh[2], rh[3]};
            MMAH(oacc[2*nt],   ph, bh0);
            MMAH(oacc[2*nt],   pl, bh0);
            MMAH(oacc[2*nt+1], ph, bh1);
            MMAH(oacc[2*nt+1], pl, bh1);
        }
    }

    // ---- normalize + store O as fp16 hi/lo ----
    const float inv0 = 1.f / l0, inv1 = 1.f / l1;
    const int r0 = w * 16 + (lane >> 2);
    const int c0 = (lane & 3) * 2;
    const size_t g0 = base + (size_t)r0 * tstride;
    const size_t g1 = g0 + 8 * tstride;
    #pragma unroll
    for (int nt = 0; nt < 8; nt++) {
        const int col = nt * 8 + c0;
        uint32_t hp, lp;
        hilo2h(oacc[nt][0] * inv0, oacc[nt][1] * inv0, hp, lp);
        *reinterpret_cast<uint32_t*>(g_Ohi + g0 + col) = hp;
        *reinterpret_cast<uint32_t*>(g_Olo + g0 + col) = lp;
        hilo2h(oacc[nt][2] * inv1, oacc[nt][3] * inv1, hp, lp);
        *reinterpret_cast<uint32_t*>(g_Ohi + g1 + col) = hp;
        *reinterpret_cast<uint32_t*>(g_Olo + g1 + col) = lp;
    }
}

// -------------------------------------------------------------------------------
extern "C" void kernel_launch(void* const* d_in, const int* in_sizes, int n_in,
                              void* d_out, int out_size) {
    const float* x      = (const float*)d_in[0];
    const float* Wq_w   = (const float*)d_in[1];
    const float* Wq_b   = (const float*)d_in[2];
    const float* Wv_w   = (const float*)d_in[3];
    const float* Wv_b   = (const float*)d_in[4];
    const float* Wk     = (const float*)d_in[5];
    const float* bk     = (const float*)d_in[6];
    const float* proj_w = (const float*)d_in[7];
    const float* proj_b = (const float*)d_in[8];
    const int*   cidraw = (const int*)d_in[9];
    float* out = (float*)d_out;

    (void)in_sizes; (void)n_in; (void)out_size;

    void *pXhi, *pXlo, *pQhi, *pQlo, *pKhi, *pVhi, *pOhi, *pOlo;
    cudaGetSymbolAddress(&pXhi, g_Xhi);
    cudaGetSymbolAddress(&pXlo, g_Xlo);
    cudaGetSymbolAddress(&pQhi, g_Qhi);
    cudaGetSymbolAddress(&pQlo, g_Qlo);
    cudaGetSymbolAddress(&pKhi, g_Khi);
    cudaGetSymbolAddress(&pVhi, g_Vhi);
    cudaGetSymbolAddress(&pOhi, g_Ohi);
    cudaGetSymbolAddress(&pOlo, g_Olo);

    cudaFuncSetAttribute(attn_mma_kernel,
                         cudaFuncAttributeMaxDynamicSharedMemorySize, ASMEM);
    cudaFuncSetAttribute(gemm_mma_kernel<0,2>,
                         cudaFuncAttributeMaxDynamicSharedMemorySize, SMEM_GEMM);
    cudaFuncSetAttribute(gemm_mma_kernel<0,1>,
                         cudaFuncAttributeMaxDynamicSharedMemorySize, SMEM_GEMM);
    cudaFuncSetAttribute(gemm_mma_kernel<1,1>,
                         cudaFuncAttributeMaxDynamicSharedMemorySize, SMEM_GEMM);
    cudaFuncSetAttribute(gemm_mma_kernel<0,0>,
                         cudaFuncAttributeMaxDynamicSharedMemorySize, SMEM_GEMM);

    decode_cid_kernel<<<1, 1>>>(cidraw);
    convert_weights_kernel<<<(NW * DD * DD) / 256, 256>>>(Wq_w, Wv_w, proj_w, Wk);
    convert_x_kernel<<<(M_TOTAL * (size_t)DD) / 1024, 256>>>(x);

    dim3 gp(4, M_TOTAL / 128);                 // n-fastest for L2 reuse of A
    gemm_mma_kernel<0,2><<<gp, 256, SMEM_GEMM>>>(
        (const __half*)pXhi, (const __half*)pXlo,
        Wq_b, nullptr, nullptr,
        (__half*)pQhi, (__half*)pQlo, 0);
    gemm_mma_kernel<0,1><<<gp, 256, SMEM_GEMM>>>(
        (const __half*)pXhi, (const __half*)pXlo,
        Wv_b, nullptr, nullptr,
        (__half*)pVhi, nullptr, 1);

    dim3 gk(4, BT / 128, NNODE);
    gemm_mma_kernel<1,1><<<gk, 256, SMEM_GEMM>>>(
        (const __half*)pXhi, (const __half*)pXlo,
        nullptr, bk, nullptr,
        (__half*)pKhi, nullptr, -1);

    attn_mma_kernel<<<BB * NNODE * HH, 384, ASMEM>>>();   // 4096 blocks

    gemm_mma_kernel<0,0><<<gp, 256, SMEM_GEMM>>>(
        (const __half*)pOhi, (const __half*)pOlo,
        proj_b, nullptr, out, nullptr, nullptr, 2);
}

// round 9
// speedup vs baseline: 3.9839x; 1.1771x over previous
#include <cuda_runtime.h>
#include <cuda_fp16.h>
#include <cstdint>

// Problem constants
#define DD    512
#define TT    192
#define NNODE 64
#define BB    8
#define HH    8
#define DHH   64
#define CC    8
#define M_TOTAL (BB*TT*NNODE)   // 98304
#define BT (BB*TT)              // 1536

// ---------------- scratch (allocation-free: __device__ globals) ----------------
__device__ int   g_cid[NNODE];
// activations: fp16 hi/lo split (A-side of GEMMs needs hi+lo; B-side hi only)
__device__ __half g_Xhi[(size_t)M_TOTAL * DD];
__device__ __half g_Xlo[(size_t)M_TOTAL * DD];
__device__ __half g_Qhi[(size_t)M_TOTAL * DD];
__device__ __half g_Qlo[(size_t)M_TOTAL * DD];
__device__ __half g_Khi[(size_t)M_TOTAL * DD];
__device__ __half g_Vhi[(size_t)M_TOTAL * DD];
__device__ __half g_Ohi[(size_t)M_TOTAL * DD];
__device__ __half g_Olo[(size_t)M_TOTAL * DD];
// weights, fp16 (hi only): [0]=Wq, [1]=Wv, [2]=proj (K-major, W[e][d]),
// [3+c] = Wk[c] transposed to K-major
#define NW 11
__device__ __half g_Wh[(size_t)NW * DD * DD];

// ================= PTX helpers (NO arch-'a' instructions: sm_80-safe) ==========
__device__ __forceinline__ uint32_t smem_u32(const void* p) {
    uint32_t a;
    asm("{ .reg .u64 t; cvta.to.shared.u64 t, %1; cvt.u32.u64 %0, t; }" : "=r"(a) : "l"(p));
    return a;
}
#define CP16(saddr, gptr) \
    asm volatile("cp.async.cg.shared.global [%0], [%1], 16;" \
        :: "r"((uint32_t)(saddr)), "l"(gptr))
#define CP_COMMIT() asm volatile("cp.async.commit_group;")
#define CP_WAIT(n)  asm volatile("cp.async.wait_group %0;" :: "n"(n))
#define LDSM4(r, addr) \
    asm volatile("ldmatrix.sync.aligned.m8n8.x4.shared.b16 {%0,%1,%2,%3}, [%4];" \
        : "=r"((r)[0]), "=r"((r)[1]), "=r"((r)[2]), "=r"((r)[3]) : "r"((uint32_t)(addr)))
#define LDSM4T(r, addr) \
    asm volatile("ldmatrix.sync.aligned.m8n8.x4.trans.shared.b16 {%0,%1,%2,%3}, [%4];" \
        : "=r"((r)[0]), "=r"((r)[1]), "=r"((r)[2]), "=r"((r)[3]) : "r"((uint32_t)(addr)))
#define MMAH(d, a, b) \
    asm volatile("mma.sync.aligned.m16n8k16.row.col.f32.f16.f16.f32 " \
        "{%0,%1,%2,%3}, {%4,%5,%6,%7}, {%8,%9}, {%0,%1,%2,%3};" \
        : "+f"((d)[0]), "+f"((d)[1]), "+f"((d)[2]), "+f"((d)[3]) \
        : "r"((a)[0]), "r"((a)[1]), "r"((a)[2]), "r"((a)[3]), \
          "r"((b)[0]), "r"((b)[1]))

__device__ __forceinline__ void hiloh(float v, uint32_t& h, uint32_t& l) {
    __half hb = __float2half_rn(v);
    h = (uint32_t)__half_as_ushort(hb);
    l = (uint32_t)__half_as_ushort(__float2half_rn(v - __half2float(hb)));
}
__device__ __forceinline__ void hilo2h(float v0, float v1, uint32_t& hp, uint32_t& lp) {
    uint32_t h0, l0, h1, l1;
    hiloh(v0, h0, l0); hiloh(v1, h1, l1);
    hp = h0 | (h1 << 16);
    lp = l0 | (l1 << 16);
}

// ---------------- cluster-id decode (handles int64 OR int32 payload) ----------
__global__ void decode_cid_kernel(const int* __restrict__ raw) {
    bool is64 = true;
    for (int i = 0; i < 32; i++) if (raw[2*i + 1] != 0) { is64 = false; break; }
    for (int i = 0; i < NNODE; i++) g_cid[i] = is64 ? raw[2*i] : raw[i];
}

// ---------------- weight conversion prepass: fp32 -> fp16 ---------------------
__global__ __launch_bounds__(256) void convert_weights_kernel(
    const float* __restrict__ Wq, const float* __restrict__ Wv,
    const float* __restrict__ proj, const float* __restrict__ Wk)
{
    int idx = blockIdx.x * 256 + threadIdx.x;
    int w = idx >> 18;
    int rc = idx & 262143;
    float v;
    if (w < 3) {
        const float* src = (w == 0) ? Wq : ((w == 1) ? Wv : proj);
        v = src[rc];
    } else {
        int e = rc >> 9, d = rc & 511;
        v = Wk[(((size_t)(w - 3)) * DD + d) * DD + e];   // transpose to K-major
    }
    g_Wh[idx] = __float2half_rn(v);
}

// ---------------- x conversion prepass: fp32 -> fp16 hi/lo --------------------
__global__ __launch_bounds__(256) void convert_x_kernel(const float* __restrict__ x) {
    size_t i = ((size_t)blockIdx.x * 256 + threadIdx.x) * 4;
    float4 v = *reinterpret_cast<const float4*>(x + i);
    uint32_t hp0, lp0, hp1, lp1;
    hilo2h(v.x, v.y, hp0, lp0);
    hilo2h(v.z, v.w, hp1, lp1);
    uint2 hp, lp;
    hp.x = hp0; hp.y = hp1; lp.x = lp0; lp.y = lp1;
    *reinterpret_cast<uint2*>(g_Xhi + i) = hp;
    *reinterpret_cast<uint2*>(g_Xlo + i) = lp;
}

// ================= mma.sync GEMM: C = A @ W^T + bias ===========================
// 2-term fp16 split: (Ahi + Alo) @ Whi. Block 64x128, 8 warps (4m x 2n),
// warp tile 16x64, K-chunk 32, 3-stage cp.async pipeline, 3 CTAs/SM.
// Row stride 80B -> conflict-free ldmatrix.
// OUT: 0 = fp32, 1 = fp16 hi only, 2 = fp16 hi+lo.
#define ROWB 80
#define A_BYTES (64 * ROWB)                 // 5120 per A sub-tensor
#define STG_BYTES (2 * A_BYTES + 128 * ROWB) // 20480 per stage (Ahi, Alo, Bh)
#define SMEM_GEMM (3 * STG_BYTES)           // 61440

template<int GROUPED, int OUT>
__global__ __launch_bounds__(256, 3) void gemm_mma_kernel(
    const __half* __restrict__ Ahi, const __half* __restrict__ Alo,
    const float* __restrict__ bias_plain, const float* __restrict__ bk,
    float* __restrict__ Cf32,
    __half* __restrict__ Chi, __half* __restrict__ Clo,
    int widx)
{
    extern __shared__ char smem[];
    const uint32_t sbase = smem_u32(smem);
    const int tid = threadIdx.x;
    const int lane = tid & 31, wid = tid >> 5;
    const int warp_m = wid & 3;       // 4 m-tiles of 16 rows
    const int warp_n = wid >> 2;      // 2 n-tiles of 64 cols
    const int n0 = blockIdx.x * 128;
    const int m0 = blockIdx.y * 64;

    int nz = 0, cid = 0;
    const __half* Bh;
    if (GROUPED) {
        nz = blockIdx.z;
        cid = g_cid[nz];
        Bh = g_Wh + (size_t)(3 + cid) * DD * DD;
    } else {
        Bh = g_Wh + (size_t)widx * DD * DD;
    }

    float acc[8][4];
    #pragma unroll
    for (int b = 0; b < 8; b++)
        #pragma unroll
        for (int c = 0; c < 4; c++) acc[b][c] = 0.f;

    auto load_chunk = [&](int kc) {
        const int k0 = kc * 32;
        const uint32_t st = sbase + (kc % 3) * STG_BYTES;
        // A: 64 rows x 32 k -> 256 x 16B, one per thread (hi + lo)
        {
            const int row = tid >> 2, c = tid & 3;
            const uint32_t so = (uint32_t)(row * ROWB + c * 16);
            size_t arow = GROUPED ? ((size_t)(m0 + row) * NNODE + nz)
                                  : (size_t)(m0 + row);
            CP16(st + so, Ahi + arow * DD + k0 + c * 8);
            CP16(st + A_BYTES + so, Alo + arow * DD + k0 + c * 8);
        }
        // B: 128 rows x 32 k -> 512 x 16B, two per thread
        #pragma unroll
        for (int i = 0; i < 2; i++) {
            const int u = tid + i * 256;
            const int row = u >> 2, c = u & 3;
            const uint32_t so = (uint32_t)(row * ROWB + c * 16);
            CP16(st + 2 * A_BYTES + so, Bh + (size_t)(n0 + row) * DD + k0 + c * 8);
        }
    };

    load_chunk(0); CP_COMMIT();
    load_chunk(1); CP_COMMIT();

    for (int kc = 0; kc < 16; kc++) {
        if (kc == 15) { CP_WAIT(0); } else { CP_WAIT(1); }
        __syncthreads();
        if (kc + 2 < 16) { load_chunk(kc + 2); CP_COMMIT(); }

        const uint32_t sa  = sbase + (kc % 3) * STG_BYTES;
        const uint32_t sal = sa + A_BYTES;
        const uint32_t sb  = sa + 2 * A_BYTES;

        #pragma unroll
        for (int ks = 0; ks < 2; ks++) {
            uint32_t ah[4], al[4], bh[8][2];
            #pragma unroll
            for (int nb = 0; nb < 4; nb++) {
                const uint32_t bo = (uint32_t)((warp_n * 64 + nb * 16 + ((lane >> 4) << 3)
                                                + (lane & 7)) * ROWB
                                               + ks * 32 + ((lane >> 3) & 1) * 16);
                uint32_t r[4];
                LDSM4(r, sb + bo);
                bh[nb*2][0] = r[0]; bh[nb*2][1] = r[1];
                bh[nb*2+1][0] = r[2]; bh[nb*2+1][1] = r[3];
            }
            {
                const uint32_t ao = (uint32_t)((warp_m * 16 + (lane & 15)) * ROWB
                                               + ks * 32 + (lane >> 4) * 16);
                LDSM4(ah, sa + ao);
                LDSM4(al, sal + ao);
            }
            #pragma unroll
            for (int nj = 0; nj < 8; nj++) {
                MMAH(acc[nj], ah, bh[nj]);
                MMAH(acc[nj], al, bh[nj]);
            }
        }
    }

    // epilogue
    const float* bias = GROUPED ? (bk + (size_t)cid * DD) : bias_plain;
    #pragma unroll
    for (int nj = 0; nj < 8; nj++) {
        const int col = n0 + warp_n * 64 + nj * 8 + (lane & 3) * 2;
        const float b0 = bias[col], b1 = bias[col + 1];
        const int r0 = m0 + warp_m * 16 + (lane >> 2);
        const size_t ro0 = GROUPED ? ((size_t)r0 * NNODE + nz) : (size_t)r0;
        const size_t ro1 = GROUPED ? ((size_t)(r0 + 8) * NNODE + nz) : (size_t)(r0 + 8);
        float v0 = acc[nj][0] + b0, v1 = acc[nj][1] + b1;
        float v2 = acc[nj][2] + b0, v3 = acc[nj][3] + b1;
        if (OUT == 2) {
            uint32_t hp, lp;
            hilo2h(v0, v1, hp, lp);
            *reinterpret_cast<uint32_t*>(Chi + ro0 * DD + col) = hp;
            *reinterpret_cast<uint32_t*>(Clo + ro0 * DD + col) = lp;
            hilo2h(v2, v3, hp, lp);
            *reinterpret_cast<uint32_t*>(Chi + ro1 * DD + col) = hp;
            *reinterpret_cast<uint32_t*>(Clo + ro1 * DD + col) = lp;
        } else if (OUT == 1) {
            __half2 h0; h0.x = __float2half_rn(v0); h0.y = __float2half_rn(v1);
            __half2 h1; h1.x = __float2half_rn(v2); h1.y = __float2half_rn(v3);
            *reinterpret_cast<__half2*>(Chi + ro0 * DD + col) = h0;
            *reinterpret_cast<__half2*>(Chi + ro1 * DD + col) = h1;
        } else {
            float2 w0; w0.x = v0; w0.y = v1;
            float2 w1; w1.x = v2; w1.y = v3;
            *reinterpret_cast<float2*>(Cf32 + ro0 * DD + col) = w0;
            *reinterpret_cast<float2*>(Cf32 + ro1 * DD + col) = w1;
        }
    }
}

// ================= tensor-core attention ======================================
// Block = (b,n,h), 384 threads (12 warps); warp w owns query rows [16w,16w+16).
// smem: Qhi, Qlo, Khi, Vhi (fp16), row stride 144B.
// S = (Qhi+Qlo)·Khi^T;  O = (Phi+Plo)·Vhi.  2-term fp16 splits.
#define AROW 144
#define ATEN (192 * AROW)            // 27648 per sub-tensor
#define ASMEM (4 * ATEN)             // 110592

__global__ __launch_bounds__(384, 1) void attn_mma_kernel() {
    extern __shared__ char smem[];
    const uint32_t sbase = smem_u32(smem);
    const int tid = threadIdx.x;
    const int lane = tid & 31, w = tid >> 5;

    const int bx = blockIdx.x;
    const int h = bx & 7;
    const int n = (bx >> 3) & 63;
    const int b = bx >> 9;
    const size_t base = ((size_t)b * TT * NNODE + n) * DD + h * DHH;
    const size_t tstride = (size_t)NNODE * DD;   // 32768

    // ---- stage Q hi/lo, K hi, V hi into smem ----
    {
        #pragma unroll
        for (int ti = 0; ti < 4; ti++) {
            const __half* tp = (ti == 0) ? (g_Qhi + base) : (ti == 1) ? (g_Qlo + base)
                             : (ti == 2) ? (g_Khi + base) : (g_Vhi + base);
            char* sp = smem + ti * ATEN;
            #pragma unroll
            for (int i = 0; i < 4; i++) {
                const int c = tid + i * 384;        // 0..1535
                const int r = c >> 3, o = c & 7;
                *reinterpret_cast<uint4*>(sp + r * AROW + o * 16) =
                    *reinterpret_cast<const uint4*>(tp + (size_t)r * tstride + o * 8);
            }
        }
    }
    __syncthreads();

    const uint32_t sQH = sbase, sQL = sbase + ATEN;
    const uint32_t sKH = sbase + 2 * ATEN;
    const uint32_t sVH = sbase + 3 * ATEN;

    // ---- preload Q fragments (16 rows x 64 k, hi+lo) ----
    uint32_t qh[4][4], ql[4][4];
    {
        const int qrow = w * 16 + (lane & 15);
        #pragma unroll
        for (int kt = 0; kt < 4; kt++) {
            const uint32_t ao = (uint32_t)(qrow * AROW + kt * 32 + (lane >> 4) * 16);
            LDSM4(qh[kt], sQH + ao);
            LDSM4(ql[kt], sQL + ao);
        }
    }

    float oacc[8][4];
    #pragma unroll
    for (int i = 0; i < 8; i++)
        #pragma unroll
        for (int j = 0; j < 4; j++) oacc[i][j] = 0.f;
    float m0 = -1e30f, m1 = -1e30f, l0 = 0.f, l1 = 0.f;

    for (int s0 = 0; s0 < TT; s0 += 16) {
        // ---- S = Q K^T (2-term) ----
        float sa0[4] = {0.f, 0.f, 0.f, 0.f};
        float sa1[4] = {0.f, 0.f, 0.f, 0.f};
        #pragma unroll
        for (int kt = 0; kt < 4; kt++) {
            const uint32_t bo = (uint32_t)((s0 + ((lane >> 4) << 3) + (lane & 7)) * AROW
                                           + kt * 32 + ((lane >> 3) & 1) * 16);
            uint32_t rh[4];
            LDSM4(rh, sKH + bo);
            uint32_t bh0[2] = {rh[0], rh[1]}, bh1[2] = {rh[2], rh[3]};
            MMAH(sa0, qh[kt], bh0);
            MMAH(sa0, ql[kt], bh0);
            MMAH(sa1, qh[kt], bh1);
            MMAH(sa1, ql[kt], bh1);
        }
        // ---- online softmax ----
        const float sc = 0.125f;
        #pragma unroll
        for (int i = 0; i < 4; i++) { sa0[i] *= sc; sa1[i] *= sc; }
        float r0m = fmaxf(fmaxf(sa0[0], sa0[1]), fmaxf(sa1[0], sa1[1]));
        float r1m = fmaxf(fmaxf(sa0[2], sa0[3]), fmaxf(sa1[2], sa1[3]));
        r0m = fmaxf(r0m, __shfl_xor_sync(0xffffffffu, r0m, 1));
        r0m = fmaxf(r0m, __shfl_xor_sync(0xffffffffu, r0m, 2));
        r1m = fmaxf(r1m, __shfl_xor_sync(0xffffffffu, r1m, 1));
        r1m = fmaxf(r1m, __shfl_xor_sync(0xffffffffu, r1m, 2));
        const float mn0 = fmaxf(m0, r0m), mn1 = fmaxf(m1, r1m);
        const float al0 = __expf(m0 - mn0), al1 = __expf(m1 - mn1);
        m0 = mn0; m1 = mn1;
        float p[8];
        p[0] = __expf(sa0[0] - mn0); p[1] = __expf(sa0[1] - mn0);
        p[2] = __expf(sa1[0] - mn0); p[3] = __expf(sa1[1] - mn0);
        p[4] = __expf(sa0[2] - mn1); p[5] = __expf(sa0[3] - mn1);
        p[6] = __expf(sa1[2] - mn1); p[7] = __expf(sa1[3] - mn1);
        float rs0 = p[0] + p[1] + p[2] + p[3];
        float rs1 = p[4] + p[5] + p[6] + p[7];
        rs0 += __shfl_xor_sync(0xffffffffu, rs0, 1);
        rs0 += __shfl_xor_sync(0xffffffffu, rs0, 2);
        rs1 += __shfl_xor_sync(0xffffffffu, rs1, 1);
        rs1 += __shfl_xor_sync(0xffffffffu, rs1, 2);
        l0 = l0 * al0 + rs0;
        l1 = l1 * al1 + rs1;
        #pragma unroll
        for (int nt = 0; nt < 8; nt++) {
            oacc[nt][0] *= al0; oacc[nt][1] *= al0;
            oacc[nt][2] *= al1; oacc[nt][3] *= al1;
        }
        // ---- pack P into A-fragments (fp16 hi/lo) ----
        uint32_t ph[4], pl[4];
        hilo2h(p[0], p[1], ph[0], pl[0]);
        hilo2h(p[4], p[5], ph[1], pl[1]);
        hilo2h(p[2], p[3], ph[2], pl[2]);
        hilo2h(p[6], p[7], ph[3], pl[3]);
        // ---- O += P V (2-term) ----
        #pragma unroll
        for (int nt = 0; nt < 4; nt++) {
            const uint32_t vo = (uint32_t)((s0 + ((lane >> 3) & 1) * 8 + (lane & 7)) * AROW
                                           + nt * 32 + (lane >> 4) * 16);
            uint32_t rh[4];
            LDSM4T(rh, sVH + vo);
            uint32_t bh0[2] = {rh[0], rh[1]}, bh1[2] = {rh[2], rh[3]};
            MMAH(oacc[2*nt],   ph, bh0);
            MMAH(oacc[2*nt],   pl, bh0);
            MMAH(oacc[2*nt+1], ph, bh1);
            MMAH(oacc[2*nt+1], pl, bh1);
        }
    }

    // ---- normalize + store O as fp16 hi/lo ----
    const float inv0 = 1.f / l0, inv1 = 1.f / l1;
    const int r0 = w * 16 + (lane >> 2);
    const int c0 = (lane & 3) * 2;
    const size_t g0 = base + (size_t)r0 * tstride;
    const size_t g1 = g0 + 8 * tstride;
    #pragma unroll
    for (int nt = 0; nt < 8; nt++) {
        const int col = nt * 8 + c0;
        uint32_t hp, lp;
        hilo2h(oacc[nt][0] * inv0, oacc[nt][1] * inv0, hp, lp);
        *reinterpret_cast<uint32_t*>(g_Ohi + g0 + col) = hp;
        *reinterpret_cast<uint32_t*>(g_Olo + g0 + col) = lp;
        hilo2h(oacc[nt][2] * inv1, oacc[nt][3] * inv1, hp, lp);
        *reinterpret_cast<uint32_t*>(g_Ohi + g1 + col) = hp;
        *reinterpret_cast<uint32_t*>(g_Olo + g1 + col) = lp;
    }
}

// -------------------------------------------------------------------------------
extern "C" void kernel_launch(void* const* d_in, const int* in_sizes, int n_in,
                              void* d_out, int out_size) {
    const float* x      = (const float*)d_in[0];
    const float* Wq_w   = (const float*)d_in[1];
    const float* Wq_b   = (const float*)d_in[2];
    const float* Wv_w   = (const float*)d_in[3];
    const float* Wv_b   = (const float*)d_in[4];
    const float* Wk     = (const float*)d_in[5];
    const float* bk     = (const float*)d_in[6];
    const float* proj_w = (const float*)d_in[7];
    const float* proj_b = (const float*)d_in[8];
    const int*   cidraw = (const int*)d_in[9];
    float* out = (float*)d_out;

    (void)in_sizes; (void)n_in; (void)out_size;

    void *pXhi, *pXlo, *pQhi, *pQlo, *pKhi, *pVhi, *pOhi, *pOlo;
    cudaGetSymbolAddress(&pXhi, g_Xhi);
    cudaGetSymbolAddress(&pXlo, g_Xlo);
    cudaGetSymbolAddress(&pQhi, g_Qhi);
    cudaGetSymbolAddress(&pQlo, g_Qlo);
    cudaGetSymbolAddress(&pKhi, g_Khi);
    cudaGetSymbolAddress(&pVhi, g_Vhi);
    cudaGetSymbolAddress(&pOhi, g_Ohi);
    cudaGetSymbolAddress(&pOlo, g_Olo);

    cudaFuncSetAttribute(attn_mma_kernel,
                         cudaFuncAttributeMaxDynamicSharedMemorySize, ASMEM);
    cudaFuncSetAttribute(gemm_mma_kernel<0,2>,
                         cudaFuncAttributeMaxDynamicSharedMemorySize, SMEM_GEMM);
    cudaFuncSetAttribute(gemm_mma_kernel<0,1>,
                         cudaFuncAttributeMaxDynamicSharedMemorySize, SMEM_GEMM);
    cudaFuncSetAttribute(gemm_mma_kernel<1,1>,
                         cudaFuncAttributeMaxDynamicSharedMemorySize, SMEM_GEMM);
    cudaFuncSetAttribute(gemm_mma_kernel<0,0>,
                         cudaFuncAttributeMaxDynamicSharedMemorySize, SMEM_GEMM);

    decode_cid_kernel<<<1, 1>>>(cidraw);
    convert_weights_kernel<<<(NW * DD * DD) / 256, 256>>>(Wq_w, Wv_w, proj_w, Wk);
    convert_x_kernel<<<(M_TOTAL * (size_t)DD) / 1024, 256>>>(x);

    dim3 gp(4, M_TOTAL / 64);                  // n-fastest for L2 reuse of A
    gemm_mma_kernel<0,2><<<gp, 256, SMEM_GEMM>>>(
        (const __half*)pXhi, (const __half*)pXlo,
        Wq_b, nullptr, nullptr,
        (__half*)pQhi, (__half*)pQlo, 0);
    gemm_mma_kernel<0,1><<<gp, 256, SMEM_GEMM>>>(
        (const __half*)pXhi, (const __half*)pXlo,
        Wv_b, nullptr, nullptr,
        (__half*)pVhi, nullptr, 1);

    dim3 gk(4, BT / 64, NNODE);
    gemm_mma_kernel<1,1><<<gk, 256, SMEM_GEMM>>>(
        (const __half*)pXhi, (const __half*)pXlo,
        nullptr, bk, nullptr,
        (__half*)pKhi, nullptr, -1);

    attn_mma_kernel<<<BB * NNODE * HH, 384, ASMEM>>>();   // 4096 blocks

    gemm_mma_kernel<0,0><<<gp, 256, SMEM_GEMM>>>(
        (const __half*)pOhi, (const __half*)pOlo,
        proj_b, nullptr, out, nullptr, nullptr, 2);
}